// round 1
// baseline (speedup 1.0000x reference)
#include <cuda_runtime.h>
#include <math.h>

// ---------------- problem constants ----------------
#define Bz    64
#define Hh    56
#define Ww    56
#define Cc    192
#define NHh   6
#define WS    7
#define SS    3
#define Nn    49          // WS*WS
#define HD    32          // C/NH
#define NW    64          // (H/WS)*(W/WS)
#define Ltok  3136        // H*W
#define Mrow  200704      // B*NW*N  == B*L
#define MLPH  768
#define QKVN  576

// ---------------- scratch (static device globals; no cudaMalloc allowed) ----
__device__ float g_yw[(size_t)Mrow * Cc];   // LN1'd, shifted, windowed tokens
__device__ float g_q [(size_t)Mrow * Cc];   // [win,NH,N,HD] (q pre-scaled)
__device__ float g_k [(size_t)Mrow * Cc];
__device__ float g_v [(size_t)Mrow * Cc];
__device__ float g_o [(size_t)Mrow * Cc];   // attention output, windowed order
__device__ float g_x1[(size_t)Mrow * Cc];   // after first residual (B,L,C)
__device__ float g_z [(size_t)Mrow * Cc];   // LN2 output
__device__ float g_hh[(size_t)Mrow * MLPH]; // fc1/gelu output

// ---------------- LN1 + cyclic shift + window partition (warp per token) ----
__global__ void ln1_shift_window_kernel(const float* __restrict__ x,
                                        const float* __restrict__ g,
                                        const float* __restrict__ b)
{
    const int warp = threadIdx.x >> 5;
    const int lane = threadIdx.x & 31;
    const int t = blockIdx.x * 8 + warp;          // windowed-token index
    const int win = t / Nn;
    const int n   = t - win * Nn;
    const int bi  = win >> 6;
    const int w_  = win & 63;
    const int wr  = w_ >> 3, wc = w_ & 7;
    const int pr  = n / WS,  pc = n - (n / WS) * WS;
    int srow = wr * WS + pr + SS; if (srow >= Hh) srow -= Hh;
    int scol = wc * WS + pc + SS; if (scol >= Ww) scol -= Ww;
    const float* xp = x + ((size_t)bi * Ltok + srow * Ww + scol) * Cc;

    float v[6], s = 0.f, ss = 0.f;
    #pragma unroll
    for (int kq = 0; kq < 6; kq++) {
        v[kq] = xp[lane + 32 * kq];
        s += v[kq]; ss += v[kq] * v[kq];
    }
    #pragma unroll
    for (int off = 16; off > 0; off >>= 1) {
        s  += __shfl_xor_sync(0xffffffffu, s,  off);
        ss += __shfl_xor_sync(0xffffffffu, ss, off);
    }
    const float mean = s * (1.f / Cc);
    const float var  = ss * (1.f / Cc) - mean * mean;
    const float rstd = rsqrtf(var + 1e-5f);

    float* op = g_yw + (size_t)t * Cc;
    #pragma unroll
    for (int kq = 0; kq < 6; kq++) {
        const int c = lane + 32 * kq;
        op[c] = (v[kq] - mean) * rstd * g[c] + b[c];
    }
}

// ---------------- LN2 (identity mapping) ----------------
__global__ void ln2_kernel(const float* __restrict__ g,
                           const float* __restrict__ b)
{
    const int warp = threadIdx.x >> 5;
    const int lane = threadIdx.x & 31;
    const int t = blockIdx.x * 8 + warp;
    const float* xp = g_x1 + (size_t)t * Cc;

    float v[6], s = 0.f, ss = 0.f;
    #pragma unroll
    for (int kq = 0; kq < 6; kq++) {
        v[kq] = xp[lane + 32 * kq];
        s += v[kq]; ss += v[kq] * v[kq];
    }
    #pragma unroll
    for (int off = 16; off > 0; off >>= 1) {
        s  += __shfl_xor_sync(0xffffffffu, s,  off);
        ss += __shfl_xor_sync(0xffffffffu, ss, off);
    }
    const float mean = s * (1.f / Cc);
    const float var  = ss * (1.f / Cc) - mean * mean;
    const float rstd = rsqrtf(var + 1e-5f);

    float* op = g_z + (size_t)t * Cc;
    #pragma unroll
    for (int kq = 0; kq < 6; kq++) {
        const int c = lane + 32 * kq;
        op[c] = (v[kq] - mean) * rstd * g[c] + b[c];
    }
}

// ---------------- shared GEMM mainloop: C[128x64] = A[M,K] @ W[N,K]^T ------
// 256 threads, 8x4 micro-tile per thread, K-tile = 16.
#define GEMM_BODY(APTR, WPTR, KDIM)                                            \
    __shared__ float As[16][129];                                              \
    __shared__ float Bs[16][65];                                               \
    const int tid = threadIdx.x;                                               \
    const int tx = tid & 15, ty = tid >> 4;                                    \
    float acc[8][4];                                                           \
    _Pragma("unroll") for (int i = 0; i < 8; i++)                              \
    _Pragma("unroll") for (int j = 0; j < 4; j++) acc[i][j] = 0.f;             \
    {                                                                          \
        const int lrA = tid >> 1, lqA = tid & 1;                               \
        const int lrB = tid >> 2, lqB = tid & 3;                               \
        const float* Ag = (APTR) + ((size_t)(blockIdx.y * 128 + lrA)) * (KDIM) \
                          + lqA * 8;                                           \
        const float* Wg = (WPTR) + ((size_t)(blockIdx.x * 64 + lrB)) * (KDIM)  \
                          + lqB * 4;                                           \
        for (int k0 = 0; k0 < (KDIM); k0 += 16) {                              \
            float4 a0 = *(const float4*)(Ag + k0);                             \
            float4 a1 = *(const float4*)(Ag + k0 + 4);                         \
            float4 b0 = *(const float4*)(Wg + k0);                             \
            As[lqA*8+0][lrA] = a0.x; As[lqA*8+1][lrA] = a0.y;                  \
            As[lqA*8+2][lrA] = a0.z; As[lqA*8+3][lrA] = a0.w;                  \
            As[lqA*8+4][lrA] = a1.x; As[lqA*8+5][lrA] = a1.y;                  \
            As[lqA*8+6][lrA] = a1.z; As[lqA*8+7][lrA] = a1.w;                  \
            Bs[lqB*4+0][lrB] = b0.x; Bs[lqB*4+1][lrB] = b0.y;                  \
            Bs[lqB*4+2][lrB] = b0.z; Bs[lqB*4+3][lrB] = b0.w;                  \
            __syncthreads();                                                   \
            _Pragma("unroll")                                                  \
            for (int kk = 0; kk < 16; kk++) {                                  \
                float a[8], bb[4];                                             \
                _Pragma("unroll") for (int i = 0; i < 8; i++)                  \
                    a[i] = As[kk][ty * 8 + i];                                 \
                _Pragma("unroll") for (int j = 0; j < 4; j++)                  \
                    bb[j] = Bs[kk][tx * 4 + j];                                \
                _Pragma("unroll") for (int i = 0; i < 8; i++)                  \
                _Pragma("unroll") for (int j = 0; j < 4; j++)                  \
                    acc[i][j] += a[i] * bb[j];                                 \
            }                                                                  \
            __syncthreads();                                                   \
        }                                                                      \
    }

// ---------------- QKV GEMM + scatter to [win,NH,N,HD] ----------------
__global__ __launch_bounds__(256) void gemm_qkv_kernel(
    const float* __restrict__ qkv_w, const float* __restrict__ qkv_b)
{
    GEMM_BODY(g_yw, qkv_w, Cc)
    #pragma unroll
    for (int i = 0; i < 8; i++) {
        const int m = blockIdx.y * 128 + ty * 8 + i;
        const int win = m / Nn;
        const int n   = m - win * Nn;
        #pragma unroll
        for (int j = 0; j < 4; j++) {
            const int co = blockIdx.x * 64 + tx * 4 + j;
            float val = acc[i][j] + qkv_b[co];
            const int part = co / Cc;
            const int c    = co - part * Cc;
            const int head = c >> 5, d = c & 31;
            const size_t dst = ((size_t)(win * NHh + head) * Nn + n) * HD + d;
            if (part == 0)      g_q[dst] = val * 0.17677669529663687f; // HD^-0.5
            else if (part == 1) g_k[dst] = val;
            else                g_v[dst] = val;
        }
    }
}

// ---------------- fused attention: one block per (window, head) ------------
__global__ __launch_bounds__(64) void attn_kernel(
    const float* __restrict__ rpb, const float* __restrict__ gate)
{
    __shared__ float sq[Nn * 33];   // padded to kill 32-way bank conflicts
    __shared__ float sk[Nn * 32];
    __shared__ float sv[Nn * 32];
    __shared__ float sb[169];

    const int wh   = blockIdx.x;          // win*NH + head
    const int win  = wh / NHh;
    const int head = wh - win * NHh;
    const int tid  = threadIdx.x;
    const size_t base = (size_t)wh * Nn * HD;

    for (int idx = tid; idx < Nn * 32; idx += 64) {
        const int r = idx >> 5, d = idx & 31;
        sq[r * 33 + d] = g_q[base + idx];
        sk[idx]        = g_k[base + idx];
        sv[idx]        = g_v[base + idx];
    }
    for (int idx = tid; idx < 169; idx += 64) sb[idx] = rpb[idx * NHh + head];
    __syncthreads();

    const float gval = 1.f / (1.f + expf(-gate[head]));
    const int i = tid;
    if (i < Nn) {
        const int w_ = win & 63;
        const int wr = w_ >> 3, wc = w_ & 7;
        const int pr = i / WS, pc = i - pr * WS;
        const int gi = ((wr < 7) ? 0 : ((pr < 4) ? 1 : 2)) * 3
                     + ((wc < 7) ? 0 : ((pc < 4) ? 1 : 2));
        float s[Nn];
        float mx = -1e30f;
        #pragma unroll 7
        for (int j = 0; j < Nn; j++) {
            float dot = 0.f;
            #pragma unroll
            for (int d = 0; d < 32; d++) dot += sq[i * 33 + d] * sk[j * 32 + d];
            const int rj = j / WS, cj = j - rj * WS;
            const int relidx = (pr - rj + 6) * 13 + (pc - cj + 6);
            const int gj = ((wr < 7) ? 0 : ((rj < 4) ? 1 : 2)) * 3
                         + ((wc < 7) ? 0 : ((cj < 4) ? 1 : 2));
            float val = dot + sb[relidx] + ((gi != gj) ? -100.f : 0.f);
            s[j] = val;
            mx = fmaxf(mx, val);
        }
        float sum = 0.f;
        #pragma unroll 7
        for (int j = 0; j < Nn; j++) { s[j] = __expf(s[j] - mx); sum += s[j]; }
        const float inv = gval / sum;

        float* op = g_o + ((size_t)win * Nn + i) * Cc + head * HD;
        #pragma unroll
        for (int d = 0; d < 32; d++) {
            float a = 0.f;
            #pragma unroll 7
            for (int j = 0; j < Nn; j++) a += s[j] * sv[j * 32 + d];
            op[d] = a * inv;
        }
    }
}

// ---------------- proj GEMM + window reverse + un-shift + residual ---------
__global__ __launch_bounds__(256) void gemm_proj_kernel(
    const float* __restrict__ proj_w, const float* __restrict__ proj_b,
    const float* __restrict__ x_shortcut)
{
    GEMM_BODY(g_o, proj_w, Cc)
    #pragma unroll
    for (int i = 0; i < 8; i++) {
        const int m = blockIdx.y * 128 + ty * 8 + i;
        const int win = m / Nn;
        const int n   = m - win * Nn;
        const int bi  = win >> 6;
        const int w_  = win & 63;
        const int wr  = w_ >> 3, wc = w_ & 7;
        const int pr  = n / WS,  pc = n - (n / WS) * WS;
        int ho = wr * WS + pr + SS; if (ho >= Hh) ho -= Hh;
        int wo = wc * WS + pc + SS; if (wo >= Ww) wo -= Ww;
        const size_t rowbase = ((size_t)bi * Ltok + ho * Ww + wo) * Cc;
        #pragma unroll
        for (int j = 0; j < 4; j++) {
            const int cn = blockIdx.x * 64 + tx * 4 + j;
            g_x1[rowbase + cn] = x_shortcut[rowbase + cn] + acc[i][j] + proj_b[cn];
        }
    }
}

// ---------------- fc1 GEMM + BN(eval) + exact GELU ----------------
__global__ __launch_bounds__(256) void gemm_fc1_kernel(
    const float* __restrict__ fc1_w, const float* __restrict__ fc1_b,
    const float* __restrict__ bn_g, const float* __restrict__ bn_b)
{
    GEMM_BODY(g_z, fc1_w, Cc)
    const float bnscale = 0.9999950000374997f; // 1/sqrt(1+1e-5)
    #pragma unroll
    for (int i = 0; i < 8; i++) {
        const int m = blockIdx.y * 128 + ty * 8 + i;
        #pragma unroll
        for (int j = 0; j < 4; j++) {
            const int cn = blockIdx.x * 64 + tx * 4 + j;
            float v = acc[i][j] + fc1_b[cn];
            v = v * bnscale * bn_g[cn] + bn_b[cn];
            v = 0.5f * v * (1.f + erff(v * 0.70710678118654752f));
            g_hh[(size_t)m * MLPH + cn] = v;
        }
    }
}

// ---------------- fc2 GEMM + residual -> final output ----------------
__global__ __launch_bounds__(256) void gemm_fc2_kernel(
    const float* __restrict__ fc2_w, const float* __restrict__ fc2_b,
    float* __restrict__ out)
{
    GEMM_BODY(g_hh, fc2_w, MLPH)
    #pragma unroll
    for (int i = 0; i < 8; i++) {
        const int m = blockIdx.y * 128 + ty * 8 + i;
        #pragma unroll
        for (int j = 0; j < 4; j++) {
            const int cn = blockIdx.x * 64 + tx * 4 + j;
            const size_t idx = (size_t)m * Cc + cn;
            out[idx] = g_x1[idx] + acc[i][j] + fc2_b[cn];
        }
    }
}

// ---------------- launch ----------------
extern "C" void kernel_launch(void* const* d_in, const int* in_sizes, int n_in,
                              void* d_out, int out_size)
{
    const float* x       = (const float*)d_in[0];
    const float* norm1_g = (const float*)d_in[1];
    const float* norm1_b = (const float*)d_in[2];
    const float* qkv_w   = (const float*)d_in[3];
    const float* qkv_b   = (const float*)d_in[4];
    const float* rpb     = (const float*)d_in[5];
    const float* gate    = (const float*)d_in[6];
    const float* proj_w  = (const float*)d_in[7];
    const float* proj_b  = (const float*)d_in[8];
    const float* norm2_g = (const float*)d_in[9];
    const float* norm2_b = (const float*)d_in[10];
    const float* fc1_w   = (const float*)d_in[11];
    const float* fc1_b   = (const float*)d_in[12];
    const float* bn_g    = (const float*)d_in[13];
    const float* bn_b    = (const float*)d_in[14];
    const float* fc2_w   = (const float*)d_in[15];
    const float* fc2_b   = (const float*)d_in[16];
    float* out = (float*)d_out;

    ln1_shift_window_kernel<<<Mrow / 8, 256>>>(x, norm1_g, norm1_b);
    gemm_qkv_kernel<<<dim3(QKVN / 64, Mrow / 128), 256>>>(qkv_w, qkv_b);
    attn_kernel<<<Bz * NW * NHh, 64>>>(rpb, gate);
    gemm_proj_kernel<<<dim3(Cc / 64, Mrow / 128), 256>>>(proj_w, proj_b, x);
    ln2_kernel<<<Mrow / 8, 256>>>(norm2_g, norm2_b);
    gemm_fc1_kernel<<<dim3(MLPH / 64, Mrow / 128), 256>>>(fc1_w, fc1_b, bn_g, bn_b);
    gemm_fc2_kernel<<<dim3(Cc / 64, Mrow / 128), 256>>>(fc2_w, fc2_b, out);
}

// round 3
// speedup vs baseline: 1.6346x; 1.6346x over previous
#include <cuda_runtime.h>
#include <cuda_bf16.h>
#include <math.h>
#include <stdint.h>

// ---------------- problem constants ----------------
#define Bz    64
#define Hh    56
#define Ww    56
#define Cc    192
#define NHh   6
#define WS    7
#define SS    3
#define Nn    49
#define HD    32
#define NW    64
#define Ltok  3136
#define Mrow  200704      // B*L == 128*1568
#define MLPH  768
#define QKVN  576

// ---------------- scratch globals ----------------
__device__ __align__(16) __nv_bfloat16 g_ywh[(size_t)Mrow * Cc];
__device__ __align__(16) __nv_bfloat16 g_ywl[(size_t)Mrow * Cc];
__device__ float g_q [(size_t)Mrow * Cc];
__device__ float g_k [(size_t)Mrow * Cc];
__device__ float g_v [(size_t)Mrow * Cc];
__device__ __align__(16) __nv_bfloat16 g_oh[(size_t)Mrow * Cc];
__device__ __align__(16) __nv_bfloat16 g_ol[(size_t)Mrow * Cc];
__device__ float g_x1[(size_t)Mrow * Cc];
__device__ __align__(16) __nv_bfloat16 g_zh[(size_t)Mrow * Cc];
__device__ __align__(16) __nv_bfloat16 g_zl[(size_t)Mrow * Cc];
__device__ __align__(16) __nv_bfloat16 g_hhh[(size_t)Mrow * MLPH];
__device__ __align__(16) __nv_bfloat16 g_hhl[(size_t)Mrow * MLPH];

// weight bf16 splits
__device__ __align__(16) __nv_bfloat16 g_qkvwh[QKVN * Cc];
__device__ __align__(16) __nv_bfloat16 g_qkvwl[QKVN * Cc];
__device__ __align__(16) __nv_bfloat16 g_projwh[Cc * Cc];
__device__ __align__(16) __nv_bfloat16 g_projwl[Cc * Cc];
__device__ __align__(16) __nv_bfloat16 g_fc1wh[MLPH * Cc];
__device__ __align__(16) __nv_bfloat16 g_fc1wl[MLPH * Cc];
__device__ __align__(16) __nv_bfloat16 g_fc2wh[Cc * MLPH];
__device__ __align__(16) __nv_bfloat16 g_fc2wl[Cc * MLPH];

// ---------------- PTX helpers (compute_103-safe: no tcgen05) -------------
__device__ __forceinline__ uint32_t smem_u32(const void* p) {
    uint32_t a;
    asm("{ .reg .u64 t; cvta.to.shared.u64 t, %1; cvt.u32.u64 %0, t; }"
        : "=r"(a) : "l"(p));
    return a;
}
__device__ __forceinline__ void cp16(uint32_t dst, const void* src) {
    asm volatile("cp.async.cg.shared.global [%0], [%1], 16;"
                 :: "r"(dst), "l"(src));
}
#define CP_COMMIT() asm volatile("cp.async.commit_group;" ::: "memory")
#define CP_WAIT2()  asm volatile("cp.async.wait_group 2;" ::: "memory")

__device__ __forceinline__ void ldm_x4(uint32_t* r, uint32_t a) {
    asm volatile("ldmatrix.sync.aligned.m8n8.x4.shared.b16 {%0,%1,%2,%3}, [%4];"
        : "=r"(r[0]), "=r"(r[1]), "=r"(r[2]), "=r"(r[3]) : "r"(a));
}
__device__ __forceinline__ void mma16816(float* d, const uint32_t* a,
                                         uint32_t b0, uint32_t b1) {
    asm volatile(
        "mma.sync.aligned.m16n8k16.row.col.f32.bf16.bf16.f32 "
        "{%0,%1,%2,%3}, {%4,%5,%6,%7}, {%8,%9}, {%0,%1,%2,%3};"
        : "+f"(d[0]), "+f"(d[1]), "+f"(d[2]), "+f"(d[3])
        : "r"(a[0]), "r"(a[1]), "r"(a[2]), "r"(a[3]), "r"(b0), "r"(b1));
}

// ---------------- GEMM geometry ----------------
// CTA tile 128(M) x 96(N), K-chunk 32 bf16, 4-stage cp.async pipeline.
// smem row stride 80B (32 bf16 data + 8 pad) -> conflict-free ldmatrix.
#define ASTR   80
#define ABYTES (128 * ASTR)     // 10240
#define BBYTES (96 * ASTR)      // 7680
#define STG    (ABYTES + BBYTES)
#define SMEM_GEMM (4 * STG)     // 71680

// 3-term bf16 split mainloop: acc = ah*bh^T + al*bh^T + ah*bl^T
__device__ __forceinline__ void gemm_mma(
    const __nv_bfloat16* __restrict__ ah, const __nv_bfloat16* __restrict__ al,
    const __nv_bfloat16* __restrict__ bh, const __nv_bfloat16* __restrict__ bl,
    int K, int n0, float (&acc)[12][4])
{
    extern __shared__ char sm[];
    const uint32_t sb = smem_u32(sm);
    const int tid  = threadIdx.x;
    const int wid  = tid >> 5, lane = tid & 31;
    const int wm   = wid >> 1, wn = wid & 1;
    const int m0   = blockIdx.y * 128;
    const int kch  = K >> 5;
    const int NCH  = 3 * kch;

    #pragma unroll
    for (int i = 0; i < 12; i++)
        #pragma unroll
        for (int j = 0; j < 4; j++) acc[i][j] = 0.f;

    auto load_stage = [&](int stg, int c) {
        const int seg = (c >= 2 * kch) ? 2 : ((c >= kch) ? 1 : 0);
        const int kc  = c - seg * kch;
        const __nv_bfloat16* A = ((seg == 1) ? al : ah) + (size_t)m0 * K + kc * 32;
        const __nv_bfloat16* B = ((seg == 2) ? bl : bh) + (size_t)n0 * K + kc * 32;
        const uint32_t Ab = sb + (uint32_t)stg * STG;
        const uint32_t Bb = Ab + ABYTES;
        #pragma unroll
        for (int i = 0; i < 2; i++) {
            const int idx = tid + i * 256;          // 512 x 16B for A
            const int r = idx >> 2, p = idx & 3;
            cp16(Ab + r * ASTR + p * 16, A + (size_t)r * K + p * 8);
        }
        {
            const int r = tid >> 2, p = tid & 3;    // first 256 x 16B for B
            cp16(Bb + r * ASTR + p * 16, B + (size_t)r * K + p * 8);
        }
        if (tid < 128) {                            // remaining 128 x 16B for B
            const int idx = tid + 256;
            const int r = idx >> 2, p = idx & 3;
            cp16(Bb + r * ASTR + p * 16, B + (size_t)r * K + p * 8);
        }
    };

    load_stage(0, 0); CP_COMMIT();
    load_stage(1, 1); CP_COMMIT();
    load_stage(2, 2); CP_COMMIT();

    const uint32_t lrow  = lane & 15;
    const uint32_t khalf = (lane >> 4) << 3;   // 0 or 8 elems

    for (int c = 0; c < NCH; c++) {
        CP_WAIT2();
        __syncthreads();
        const uint32_t Ab = sb + (uint32_t)(c & 3) * STG;
        const uint32_t Bb = Ab + ABYTES;
        #pragma unroll
        for (int ks = 0; ks < 2; ks++) {
            uint32_t rA[2][4], rB[3][4];
            const uint32_t koff = (ks * 16 + khalf) * 2;
            #pragma unroll
            for (int mi = 0; mi < 2; mi++)
                ldm_x4(rA[mi], Ab + (wm * 32 + mi * 16 + lrow) * ASTR + koff);
            #pragma unroll
            for (int ni = 0; ni < 3; ni++)
                ldm_x4(rB[ni], Bb + (wn * 48 + ni * 16 + lrow) * ASTR + koff);
            #pragma unroll
            for (int mi = 0; mi < 2; mi++)
                #pragma unroll
                for (int nj = 0; nj < 6; nj++)
                    mma16816(acc[mi * 6 + nj], rA[mi],
                             rB[nj >> 1][nj & 1], rB[nj >> 1][(nj & 1) + 2]);
        }
        if (c + 3 < NCH) load_stage((c + 3) & 3, c + 3);
        CP_COMMIT();
    }
}

// epilogue index helpers (warp tile 32x48, frag rows g/g+8, col pair tg*2)
#define EPI_PROLOGUE()                                          \
    const int tid = threadIdx.x;                                \
    const int wid = tid >> 5, lane = tid & 31;                  \
    const int wm = wid >> 1, wn = wid & 1;                      \
    const int g = lane >> 2, tg = lane & 3;                     \
    const int m0 = blockIdx.y * 128;

// ---------------- QKV GEMM + scatter ----------------
__global__ __launch_bounds__(256) void gemm_qkv_kernel(const float* __restrict__ qkv_b)
{
    float acc[12][4];
    gemm_mma(g_ywh, g_ywl, g_qkvwh, g_qkvwl, Cc, blockIdx.x * 96, acc);
    EPI_PROLOGUE();
    const int part = blockIdx.x >> 1;          // N tiles 0-1:q 2-3:k 4-5:v
    float* dst = (part == 0) ? g_q : ((part == 1) ? g_k : g_v);
    const float sc = (part == 0) ? 0.17677669529663687f : 1.0f;
    const int cbase = (blockIdx.x & 1) * 96 + wn * 48;
    #pragma unroll
    for (int t = 0; t < 12; t++) {
        const int mi = t / 6, nj = t % 6;
        const int c = cbase + nj * 8 + tg * 2;
        const float b0 = qkv_b[part * 192 + c];
        const float b1 = qkv_b[part * 192 + c + 1];
        const int head = c >> 5, d = c & 31;
        #pragma unroll
        for (int h = 0; h < 2; h++) {
            const int m = m0 + wm * 32 + mi * 16 + g + h * 8;
            const int win = m / Nn, n = m - win * Nn;
            const size_t o = ((size_t)(win * NHh + head) * Nn + n) * HD + d;
            *(float2*)(dst + o) = make_float2((acc[t][h * 2 + 0] + b0) * sc,
                                              (acc[t][h * 2 + 1] + b1) * sc);
        }
    }
}

// ---------------- proj GEMM + window reverse + un-shift + residual --------
__global__ __launch_bounds__(256) void gemm_proj_kernel(
    const float* __restrict__ proj_b, const float* __restrict__ x_shortcut)
{
    float acc[12][4];
    gemm_mma(g_oh, g_ol, g_projwh, g_projwl, Cc, blockIdx.x * 96, acc);
    EPI_PROLOGUE();
    const int cbase = blockIdx.x * 96 + wn * 48;
    #pragma unroll
    for (int t = 0; t < 12; t++) {
        const int mi = t / 6, nj = t % 6;
        const int cn = cbase + nj * 8 + tg * 2;
        const float b0 = proj_b[cn], b1 = proj_b[cn + 1];
        #pragma unroll
        for (int h = 0; h < 2; h++) {
            const int m = m0 + wm * 32 + mi * 16 + g + h * 8;
            const int win = m / Nn, n = m - win * Nn;
            const int bi = win >> 6, w_ = win & 63;
            const int wr = w_ >> 3, wc = w_ & 7;
            const int pr = n / WS, pc = n - pr * WS;
            int ho = wr * WS + pr + SS; if (ho >= Hh) ho -= Hh;
            int wo = wc * WS + pc + SS; if (wo >= Ww) wo -= Ww;
            const size_t gi = ((size_t)bi * Ltok + ho * Ww + wo) * Cc + cn;
            float2 xs = *(const float2*)(x_shortcut + gi);
            *(float2*)(g_x1 + gi) = make_float2(xs.x + acc[t][h * 2 + 0] + b0,
                                                xs.y + acc[t][h * 2 + 1] + b1);
        }
    }
}

// ---------------- fc1 GEMM + BN(eval) + exact GELU -> bf16 split ----------
__global__ __launch_bounds__(256) void gemm_fc1_kernel(
    const float* __restrict__ fc1_b, const float* __restrict__ bn_g,
    const float* __restrict__ bn_b)
{
    float acc[12][4];
    gemm_mma(g_zh, g_zl, g_fc1wh, g_fc1wl, Cc, blockIdx.x * 96, acc);
    EPI_PROLOGUE();
    const float bnscale = 0.9999950000374997f;  // 1/sqrt(1+1e-5)
    const int cbase = blockIdx.x * 96 + wn * 48;
    #pragma unroll
    for (int t = 0; t < 12; t++) {
        const int mi = t / 6, nj = t % 6;
        const int cn = cbase + nj * 8 + tg * 2;
        const float fb0 = fc1_b[cn],  fb1 = fc1_b[cn + 1];
        const float sg0 = bnscale * bn_g[cn], sg1 = bnscale * bn_g[cn + 1];
        const float bb0 = bn_b[cn], bb1 = bn_b[cn + 1];
        #pragma unroll
        for (int h = 0; h < 2; h++) {
            const int m = m0 + wm * 32 + mi * 16 + g + h * 8;
            float v0 = (acc[t][h * 2 + 0] + fb0) * sg0 + bb0;
            float v1 = (acc[t][h * 2 + 1] + fb1) * sg1 + bb1;
            v0 = 0.5f * v0 * (1.f + erff(v0 * 0.70710678118654752f));
            v1 = 0.5f * v1 * (1.f + erff(v1 * 0.70710678118654752f));
            __nv_bfloat16 h0 = __float2bfloat16(v0);
            __nv_bfloat16 h1 = __float2bfloat16(v1);
            __nv_bfloat16 l0 = __float2bfloat16(v0 - __bfloat162float(h0));
            __nv_bfloat16 l1 = __float2bfloat16(v1 - __bfloat162float(h1));
            const size_t o = (size_t)m * MLPH + cn;
            *(__nv_bfloat162*)(g_hhh + o) = __halves2bfloat162(h0, h1);
            *(__nv_bfloat162*)(g_hhl + o) = __halves2bfloat162(l0, l1);
        }
    }
}

// ---------------- fc2 GEMM + residual -> output ----------------
__global__ __launch_bounds__(256) void gemm_fc2_kernel(
    const float* __restrict__ fc2_b, float* __restrict__ out)
{
    float acc[12][4];
    gemm_mma(g_hhh, g_hhl, g_fc2wh, g_fc2wl, MLPH, blockIdx.x * 96, acc);
    EPI_PROLOGUE();
    const int cbase = blockIdx.x * 96 + wn * 48;
    #pragma unroll
    for (int t = 0; t < 12; t++) {
        const int mi = t / 6, nj = t % 6;
        const int cn = cbase + nj * 8 + tg * 2;
        const float b0 = fc2_b[cn], b1 = fc2_b[cn + 1];
        #pragma unroll
        for (int h = 0; h < 2; h++) {
            const int m = m0 + wm * 32 + mi * 16 + g + h * 8;
            const size_t o = (size_t)m * Cc + cn;
            float2 xs = *(const float2*)(g_x1 + o);
            *(float2*)(out + o) = make_float2(xs.x + acc[t][h * 2 + 0] + b0,
                                              xs.y + acc[t][h * 2 + 1] + b1);
        }
    }
}

// ---------------- LN1 + shift + window -> bf16 split ----------------
__global__ void ln1_shift_window_kernel(const float* __restrict__ x,
                                        const float* __restrict__ g,
                                        const float* __restrict__ b)
{
    const int warp = threadIdx.x >> 5;
    const int lane = threadIdx.x & 31;
    const int t = blockIdx.x * 8 + warp;
    const int win = t / Nn;
    const int n   = t - win * Nn;
    const int bi  = win >> 6;
    const int w_  = win & 63;
    const int wr  = w_ >> 3, wc = w_ & 7;
    const int pr  = n / WS,  pc = n - (n / WS) * WS;
    int srow = wr * WS + pr + SS; if (srow >= Hh) srow -= Hh;
    int scol = wc * WS + pc + SS; if (scol >= Ww) scol -= Ww;
    const float* xp = x + ((size_t)bi * Ltok + srow * Ww + scol) * Cc;

    float v[6], s = 0.f, ss = 0.f;
    #pragma unroll
    for (int kq = 0; kq < 6; kq++) { v[kq] = xp[lane + 32 * kq]; s += v[kq]; ss += v[kq] * v[kq]; }
    #pragma unroll
    for (int off = 16; off > 0; off >>= 1) {
        s  += __shfl_xor_sync(0xffffffffu, s,  off);
        ss += __shfl_xor_sync(0xffffffffu, ss, off);
    }
    const float mean = s * (1.f / Cc);
    const float rstd = rsqrtf(ss * (1.f / Cc) - mean * mean + 1e-5f);
    #pragma unroll
    for (int kq = 0; kq < 6; kq++) {
        const int c = lane + 32 * kq;
        const float val = (v[kq] - mean) * rstd * g[c] + b[c];
        __nv_bfloat16 hi = __float2bfloat16(val);
        g_ywh[(size_t)t * Cc + c] = hi;
        g_ywl[(size_t)t * Cc + c] = __float2bfloat16(val - __bfloat162float(hi));
    }
}

// ---------------- LN2 -> bf16 split ----------------
__global__ void ln2_kernel(const float* __restrict__ g, const float* __restrict__ b)
{
    const int warp = threadIdx.x >> 5;
    const int lane = threadIdx.x & 31;
    const int t = blockIdx.x * 8 + warp;
    const float* xp = g_x1 + (size_t)t * Cc;

    float v[6], s = 0.f, ss = 0.f;
    #pragma unroll
    for (int kq = 0; kq < 6; kq++) { v[kq] = xp[lane + 32 * kq]; s += v[kq]; ss += v[kq] * v[kq]; }
    #pragma unroll
    for (int off = 16; off > 0; off >>= 1) {
        s  += __shfl_xor_sync(0xffffffffu, s,  off);
        ss += __shfl_xor_sync(0xffffffffu, ss, off);
    }
    const float mean = s * (1.f / Cc);
    const float rstd = rsqrtf(ss * (1.f / Cc) - mean * mean + 1e-5f);
    #pragma unroll
    for (int kq = 0; kq < 6; kq++) {
        const int c = lane + 32 * kq;
        const float val = (v[kq] - mean) * rstd * g[c] + b[c];
        __nv_bfloat16 hi = __float2bfloat16(val);
        g_zh[(size_t)t * Cc + c] = hi;
        g_zl[(size_t)t * Cc + c] = __float2bfloat16(val - __bfloat162float(hi));
    }
}

// ---------------- fused attention per (window, head) ----------------
__global__ __launch_bounds__(64) void attn_kernel(
    const float* __restrict__ rpb, const float* __restrict__ gate)
{
    __shared__ float sq[Nn * 33];
    __shared__ float sk[Nn * 32];
    __shared__ float sv[Nn * 32];
    __shared__ float sb[169];

    const int wh   = blockIdx.x;
    const int win  = wh / NHh;
    const int head = wh - win * NHh;
    const int tid  = threadIdx.x;
    const size_t base = (size_t)wh * Nn * HD;

    for (int idx = tid; idx < Nn * 32; idx += 64) {
        const int r = idx >> 5, d = idx & 31;
        sq[r * 33 + d] = g_q[base + idx];
        sk[idx]        = g_k[base + idx];
        sv[idx]        = g_v[base + idx];
    }
    for (int idx = tid; idx < 169; idx += 64) sb[idx] = rpb[idx * NHh + head];
    __syncthreads();

    const float gval = 1.f / (1.f + expf(-gate[head]));
    const int i = tid;
    if (i < Nn) {
        const int w_ = win & 63;
        const int wr = w_ >> 3, wc = w_ & 7;
        const int pr = i / WS, pc = i - pr * WS;
        const int gi = ((wr < 7) ? 0 : ((pr < 4) ? 1 : 2)) * 3
                     + ((wc < 7) ? 0 : ((pc < 4) ? 1 : 2));
        float s[Nn];
        float mx = -1e30f;
        #pragma unroll 7
        for (int j = 0; j < Nn; j++) {
            float dot = 0.f;
            #pragma unroll
            for (int d = 0; d < 32; d++) dot += sq[i * 33 + d] * sk[j * 32 + d];
            const int rj = j / WS, cj = j - rj * WS;
            const int relidx = (pr - rj + 6) * 13 + (pc - cj + 6);
            const int gj = ((wr < 7) ? 0 : ((rj < 4) ? 1 : 2)) * 3
                         + ((wc < 7) ? 0 : ((cj < 4) ? 1 : 2));
            float val = dot + sb[relidx] + ((gi != gj) ? -100.f : 0.f);
            s[j] = val;
            mx = fmaxf(mx, val);
        }
        float sum = 0.f;
        #pragma unroll 7
        for (int j = 0; j < Nn; j++) { s[j] = __expf(s[j] - mx); sum += s[j]; }
        const float inv = gval / sum;

        const size_t ob = ((size_t)win * Nn + i) * Cc + head * HD;
        #pragma unroll
        for (int d = 0; d < 32; d++) {
            float a = 0.f;
            #pragma unroll 7
            for (int j = 0; j < Nn; j++) a += s[j] * sv[j * 32 + d];
            a *= inv;
            __nv_bfloat16 hi = __float2bfloat16(a);
            g_oh[ob + d] = hi;
            g_ol[ob + d] = __float2bfloat16(a - __bfloat162float(hi));
        }
    }
}

// ---------------- weight fp32 -> bf16 split ----------------
__global__ void split_kernel(const float* __restrict__ s,
                             __nv_bfloat16* __restrict__ h,
                             __nv_bfloat16* __restrict__ l, int n)
{
    const int i = blockIdx.x * 256 + threadIdx.x;
    if (i < n) {
        const float v = s[i];
        __nv_bfloat16 hi = __float2bfloat16(v);
        h[i] = hi;
        l[i] = __float2bfloat16(v - __bfloat162float(hi));
    }
}

// ---------------- launch ----------------
extern "C" void kernel_launch(void* const* d_in, const int* in_sizes, int n_in,
                              void* d_out, int out_size)
{
    const float* x       = (const float*)d_in[0];
    const float* norm1_g = (const float*)d_in[1];
    const float* norm1_b = (const float*)d_in[2];
    const float* qkv_w   = (const float*)d_in[3];
    const float* qkv_b   = (const float*)d_in[4];
    const float* rpb     = (const float*)d_in[5];
    const float* gate    = (const float*)d_in[6];
    const float* proj_w  = (const float*)d_in[7];
    const float* proj_b  = (const float*)d_in[8];
    const float* norm2_g = (const float*)d_in[9];
    const float* norm2_b = (const float*)d_in[10];
    const float* fc1_w   = (const float*)d_in[11];
    const float* fc1_b   = (const float*)d_in[12];
    const float* bn_g    = (const float*)d_in[13];
    const float* bn_b    = (const float*)d_in[14];
    const float* fc2_w   = (const float*)d_in[15];
    const float* fc2_b   = (const float*)d_in[16];
    float* out = (float*)d_out;

    static bool attr_done = false;
    if (!attr_done) {
        cudaFuncSetAttribute(gemm_qkv_kernel,  cudaFuncAttributeMaxDynamicSharedMemorySize, SMEM_GEMM);
        cudaFuncSetAttribute(gemm_proj_kernel, cudaFuncAttributeMaxDynamicSharedMemorySize, SMEM_GEMM);
        cudaFuncSetAttribute(gemm_fc1_kernel,  cudaFuncAttributeMaxDynamicSharedMemorySize, SMEM_GEMM);
        cudaFuncSetAttribute(gemm_fc2_kernel,  cudaFuncAttributeMaxDynamicSharedMemorySize, SMEM_GEMM);
        attr_done = true;
    }

    __nv_bfloat16 *qwh, *qwl, *pwh, *pwl, *f1h, *f1l, *f2h, *f2l;
    cudaGetSymbolAddress((void**)&qwh, g_qkvwh);  cudaGetSymbolAddress((void**)&qwl, g_qkvwl);
    cudaGetSymbolAddress((void**)&pwh, g_projwh); cudaGetSymbolAddress((void**)&pwl, g_projwl);
    cudaGetSymbolAddress((void**)&f1h, g_fc1wh);  cudaGetSymbolAddress((void**)&f1l, g_fc1wl);
    cudaGetSymbolAddress((void**)&f2h, g_fc2wh);  cudaGetSymbolAddress((void**)&f2l, g_fc2wl);

    split_kernel<<<(QKVN * Cc + 255) / 256, 256>>>(qkv_w, qwh, qwl, QKVN * Cc);
    split_kernel<<<(Cc * Cc + 255) / 256, 256>>>(proj_w, pwh, pwl, Cc * Cc);
    split_kernel<<<(MLPH * Cc + 255) / 256, 256>>>(fc1_w, f1h, f1l, MLPH * Cc);
    split_kernel<<<(Cc * MLPH + 255) / 256, 256>>>(fc2_w, f2h, f2l, Cc * MLPH);

    ln1_shift_window_kernel<<<Mrow / 8, 256>>>(x, norm1_g, norm1_b);
    gemm_qkv_kernel<<<dim3(QKVN / 96, Mrow / 128), 256, SMEM_GEMM>>>(qkv_b);
    attn_kernel<<<Bz * NW * NHh, 64>>>(rpb, gate);
    gemm_proj_kernel<<<dim3(Cc / 96, Mrow / 128), 256, SMEM_GEMM>>>(proj_b, x);
    ln2_kernel<<<Mrow / 8, 256>>>(norm2_g, norm2_b);
    gemm_fc1_kernel<<<dim3(MLPH / 96, Mrow / 128), 256, SMEM_GEMM>>>(fc1_b, bn_g, bn_b);
    gemm_fc2_kernel<<<dim3(Cc / 96, Mrow / 128), 256, SMEM_GEMM>>>(fc2_b, out);
}

// round 4
// speedup vs baseline: 1.8733x; 1.1461x over previous
#include <cuda_runtime.h>
#include <cuda_bf16.h>
#include <math.h>
#include <stdint.h>

// ---------------- problem constants ----------------
#define Bz    64
#define Hh    56
#define Ww    56
#define Cc    192
#define NHh   6
#define WS    7
#define SS    3
#define Nn    49
#define HD    32
#define NW    64
#define Ltok  3136
#define Mrow  200704      // B*L == 128*1568
#define MLPH  768
#define QKVN  576

// ---------------- scratch globals ----------------
__device__ __align__(16) __nv_bfloat16 g_ywh[(size_t)Mrow * Cc];
__device__ __align__(16) __nv_bfloat16 g_ywl[(size_t)Mrow * Cc];
__device__ __align__(16) __nv_bfloat16 g_qh[(size_t)Mrow * Cc];
__device__ __align__(16) __nv_bfloat16 g_ql[(size_t)Mrow * Cc];
__device__ __align__(16) __nv_bfloat16 g_kh[(size_t)Mrow * Cc];
__device__ __align__(16) __nv_bfloat16 g_kl[(size_t)Mrow * Cc];
__device__ __align__(16) __nv_bfloat16 g_vh[(size_t)Mrow * Cc];
__device__ __align__(16) __nv_bfloat16 g_vl[(size_t)Mrow * Cc];
__device__ __align__(16) __nv_bfloat16 g_oh[(size_t)Mrow * Cc];
__device__ __align__(16) __nv_bfloat16 g_ol[(size_t)Mrow * Cc];
__device__ float g_x1[(size_t)Mrow * Cc];
__device__ __align__(16) __nv_bfloat16 g_zh[(size_t)Mrow * Cc];
__device__ __align__(16) __nv_bfloat16 g_zl[(size_t)Mrow * Cc];
__device__ __align__(16) __nv_bfloat16 g_hhh[(size_t)Mrow * MLPH];
__device__ __align__(16) __nv_bfloat16 g_hhl[(size_t)Mrow * MLPH];

// weight bf16 splits
__device__ __align__(16) __nv_bfloat16 g_qkvwh[QKVN * Cc];
__device__ __align__(16) __nv_bfloat16 g_qkvwl[QKVN * Cc];
__device__ __align__(16) __nv_bfloat16 g_projwh[Cc * Cc];
__device__ __align__(16) __nv_bfloat16 g_projwl[Cc * Cc];
__device__ __align__(16) __nv_bfloat16 g_fc1wh[MLPH * Cc];
__device__ __align__(16) __nv_bfloat16 g_fc1wl[MLPH * Cc];
__device__ __align__(16) __nv_bfloat16 g_fc2wh[Cc * MLPH];
__device__ __align__(16) __nv_bfloat16 g_fc2wl[Cc * MLPH];

// ---------------- PTX helpers ----------------
__device__ __forceinline__ uint32_t smem_u32(const void* p) {
    uint32_t a;
    asm("{ .reg .u64 t; cvta.to.shared.u64 t, %1; cvt.u32.u64 %0, t; }"
        : "=r"(a) : "l"(p));
    return a;
}
__device__ __forceinline__ void cp16(uint32_t dst, const void* src) {
    asm volatile("cp.async.cg.shared.global [%0], [%1], 16;"
                 :: "r"(dst), "l"(src));
}
#define CP_COMMIT() asm volatile("cp.async.commit_group;" ::: "memory")
#define CP_WAIT2()  asm volatile("cp.async.wait_group 2;" ::: "memory")

__device__ __forceinline__ void ldm_x4(uint32_t* r, uint32_t a) {
    asm volatile("ldmatrix.sync.aligned.m8n8.x4.shared.b16 {%0,%1,%2,%3}, [%4];"
        : "=r"(r[0]), "=r"(r[1]), "=r"(r[2]), "=r"(r[3]) : "r"(a));
}
__device__ __forceinline__ void mma16816(float* d, const uint32_t* a,
                                         uint32_t b0, uint32_t b1) {
    asm volatile(
        "mma.sync.aligned.m16n8k16.row.col.f32.bf16.bf16.f32 "
        "{%0,%1,%2,%3}, {%4,%5,%6,%7}, {%8,%9}, {%0,%1,%2,%3};"
        : "+f"(d[0]), "+f"(d[1]), "+f"(d[2]), "+f"(d[3])
        : "r"(a[0]), "r"(a[1]), "r"(a[2]), "r"(a[3]), "r"(b0), "r"(b1));
}
__device__ __forceinline__ void split2(float v0, float v1,
                                       uint32_t& h, uint32_t& l) {
    __nv_bfloat162 hh;
    hh.x = __float2bfloat16(v0); hh.y = __float2bfloat16(v1);
    __nv_bfloat162 ll;
    ll.x = __float2bfloat16(v0 - __bfloat162float(hh.x));
    ll.y = __float2bfloat16(v1 - __bfloat162float(hh.y));
    h = *(uint32_t*)&hh; l = *(uint32_t*)&ll;
}

// ---------------- GEMM geometry ----------------
// CTA tile 128(M) x 192(N), warps 2(m) x 4(n), warp tile 64x48.
// K-chunk 32 bf16, 4-stage cp.async pipeline. smem row stride 80B.
#define ASTR   80
#define ABYTES (128 * ASTR)     // 10240
#define BBYTES (192 * ASTR)     // 15360
#define STG    (ABYTES + BBYTES)
#define SMEM_GEMM (4 * STG)     // 102400

// 3-term bf16 split mainloop: acc = ah*bh^T + al*bh^T + ah*bl^T
__device__ __forceinline__ void gemm_mma(
    const __nv_bfloat16* __restrict__ ah, const __nv_bfloat16* __restrict__ al,
    const __nv_bfloat16* __restrict__ bh, const __nv_bfloat16* __restrict__ bl,
    int K, int n0, float (&acc)[24][4])
{
    extern __shared__ char sm[];
    const uint32_t sb = smem_u32(sm);
    const int tid  = threadIdx.x;
    const int wid  = tid >> 5, lane = tid & 31;
    const int wm   = wid >> 2, wn = wid & 3;
    const int m0   = blockIdx.y * 128;
    const int kch  = K >> 5;
    const int NCH  = 3 * kch;

    #pragma unroll
    for (int i = 0; i < 24; i++)
        #pragma unroll
        for (int j = 0; j < 4; j++) acc[i][j] = 0.f;

    auto load_stage = [&](int stg, int c) {
        const int seg = (c >= 2 * kch) ? 2 : ((c >= kch) ? 1 : 0);
        const int kc  = c - seg * kch;
        const __nv_bfloat16* A = ((seg == 1) ? al : ah) + (size_t)m0 * K + kc * 32;
        const __nv_bfloat16* B = ((seg == 2) ? bl : bh) + (size_t)n0 * K + kc * 32;
        const uint32_t Ab = sb + (uint32_t)stg * STG;
        const uint32_t Bb = Ab + ABYTES;
        #pragma unroll
        for (int i = 0; i < 2; i++) {
            const int idx = tid + i * 256;          // 512 x 16B for A
            const int r = idx >> 2, p = idx & 3;
            cp16(Ab + r * ASTR + p * 16, A + (size_t)r * K + p * 8);
        }
        #pragma unroll
        for (int i = 0; i < 3; i++) {               // 768 x 16B for B
            const int idx = tid + i * 256;
            const int r = idx >> 2, p = idx & 3;
            cp16(Bb + r * ASTR + p * 16, B + (size_t)r * K + p * 8);
        }
    };

    load_stage(0, 0); CP_COMMIT();
    load_stage(1, 1); CP_COMMIT();
    load_stage(2, 2); CP_COMMIT();

    const uint32_t lrow  = lane & 15;
    const uint32_t koffh = (lane >> 4) << 4;   // byte offset of k-half

    for (int c = 0; c < NCH; c++) {
        CP_WAIT2();
        __syncthreads();
        const uint32_t Ab = sb + (uint32_t)(c & 3) * STG;
        const uint32_t Bb = Ab + ABYTES;
        #pragma unroll
        for (int ks = 0; ks < 2; ks++) {
            uint32_t rA[4][4], rB[3][4];
            const uint32_t koff = ks * 32 + koffh;
            #pragma unroll
            for (int mi = 0; mi < 4; mi++)
                ldm_x4(rA[mi], Ab + (wm * 64 + mi * 16 + lrow) * ASTR + koff);
            #pragma unroll
            for (int ni = 0; ni < 3; ni++)
                ldm_x4(rB[ni], Bb + (wn * 48 + ni * 16 + lrow) * ASTR + koff);
            #pragma unroll
            for (int mi = 0; mi < 4; mi++)
                #pragma unroll
                for (int nj = 0; nj < 6; nj++)
                    mma16816(acc[mi * 6 + nj], rA[mi],
                             rB[nj >> 1][nj & 1], rB[nj >> 1][(nj & 1) + 2]);
        }
        if (c + 3 < NCH) load_stage((c + 3) & 3, c + 3);
        CP_COMMIT();
    }
}

#define EPI_PROLOGUE()                                          \
    const int tid = threadIdx.x;                                \
    const int wid = tid >> 5, lane = tid & 31;                  \
    const int wm = wid >> 2, wn = wid & 3;                      \
    const int g = lane >> 2, tg = lane & 3;                     \
    const int m0 = blockIdx.y * 128;

// ---------------- QKV GEMM + scatter to bf16-split q/k/v ----------------
__global__ __launch_bounds__(256) void gemm_qkv_kernel(const float* __restrict__ qkv_b)
{
    float acc[24][4];
    gemm_mma(g_ywh, g_ywl, g_qkvwh, g_qkvwl, Cc, blockIdx.x * 192, acc);
    EPI_PROLOGUE();
    const int part = blockIdx.x;  // 0:q 1:k 2:v
    __nv_bfloat16* dh = (part == 0) ? g_qh : ((part == 1) ? g_kh : g_vh);
    __nv_bfloat16* dl = (part == 0) ? g_ql : ((part == 1) ? g_kl : g_vl);
    const float sc = (part == 0) ? 0.17677669529663687f : 1.0f;
    #pragma unroll
    for (int t = 0; t < 24; t++) {
        const int mi = t / 6, nj = t % 6;
        const int c = wn * 48 + nj * 8 + tg * 2;
        const float b0 = qkv_b[part * 192 + c];
        const float b1 = qkv_b[part * 192 + c + 1];
        const int head = c >> 5, d = c & 31;
        #pragma unroll
        for (int h = 0; h < 2; h++) {
            const int m = m0 + wm * 64 + mi * 16 + g + h * 8;
            const int win = m / Nn, n = m - win * Nn;
            const size_t o = ((size_t)(win * NHh + head) * Nn + n) * HD + d;
            uint32_t ph, pl;
            split2((acc[t][h * 2 + 0] + b0) * sc, (acc[t][h * 2 + 1] + b1) * sc, ph, pl);
            *(uint32_t*)(dh + o) = ph;
            *(uint32_t*)(dl + o) = pl;
        }
    }
}

// ---------------- proj GEMM + window reverse + un-shift + residual --------
__global__ __launch_bounds__(256) void gemm_proj_kernel(
    const float* __restrict__ proj_b, const float* __restrict__ x_shortcut)
{
    float acc[24][4];
    gemm_mma(g_oh, g_ol, g_projwh, g_projwl, Cc, 0, acc);
    EPI_PROLOGUE();
    #pragma unroll
    for (int t = 0; t < 24; t++) {
        const int mi = t / 6, nj = t % 6;
        const int cn = wn * 48 + nj * 8 + tg * 2;
        const float b0 = proj_b[cn], b1 = proj_b[cn + 1];
        #pragma unroll
        for (int h = 0; h < 2; h++) {
            const int m = m0 + wm * 64 + mi * 16 + g + h * 8;
            const int win = m / Nn, n = m - win * Nn;
            const int bi = win >> 6, w_ = win & 63;
            const int wr = w_ >> 3, wc = w_ & 7;
            const int pr = n / WS, pc = n - pr * WS;
            int ho = wr * WS + pr + SS; if (ho >= Hh) ho -= Hh;
            int wo = wc * WS + pc + SS; if (wo >= Ww) wo -= Ww;
            const size_t gi = ((size_t)bi * Ltok + ho * Ww + wo) * Cc + cn;
            float2 xs = *(const float2*)(x_shortcut + gi);
            *(float2*)(g_x1 + gi) = make_float2(xs.x + acc[t][h * 2 + 0] + b0,
                                                xs.y + acc[t][h * 2 + 1] + b1);
        }
    }
}

// ---------------- fc1 GEMM + BN(eval) + exact GELU -> bf16 split ----------
__global__ __launch_bounds__(256) void gemm_fc1_kernel(
    const float* __restrict__ fc1_b, const float* __restrict__ bn_g,
    const float* __restrict__ bn_b)
{
    float acc[24][4];
    gemm_mma(g_zh, g_zl, g_fc1wh, g_fc1wl, Cc, blockIdx.x * 192, acc);
    EPI_PROLOGUE();
    const float bnscale = 0.9999950000374997f;  // 1/sqrt(1+1e-5)
    #pragma unroll
    for (int t = 0; t < 24; t++) {
        const int mi = t / 6, nj = t % 6;
        const int cn = blockIdx.x * 192 + wn * 48 + nj * 8 + tg * 2;
        const float fb0 = fc1_b[cn],  fb1 = fc1_b[cn + 1];
        const float sg0 = bnscale * bn_g[cn], sg1 = bnscale * bn_g[cn + 1];
        const float bb0 = bn_b[cn], bb1 = bn_b[cn + 1];
        #pragma unroll
        for (int h = 0; h < 2; h++) {
            const int m = m0 + wm * 64 + mi * 16 + g + h * 8;
            float v0 = (acc[t][h * 2 + 0] + fb0) * sg0 + bb0;
            float v1 = (acc[t][h * 2 + 1] + fb1) * sg1 + bb1;
            v0 = 0.5f * v0 * (1.f + erff(v0 * 0.70710678118654752f));
            v1 = 0.5f * v1 * (1.f + erff(v1 * 0.70710678118654752f));
            uint32_t ph, pl;
            split2(v0, v1, ph, pl);
            const size_t o = (size_t)m * MLPH + cn;
            *(uint32_t*)(g_hhh + o) = ph;
            *(uint32_t*)(g_hhl + o) = pl;
        }
    }
}

// ---------------- fc2 GEMM + residual -> output ----------------
__global__ __launch_bounds__(256) void gemm_fc2_kernel(
    const float* __restrict__ fc2_b, float* __restrict__ out)
{
    float acc[24][4];
    gemm_mma(g_hhh, g_hhl, g_fc2wh, g_fc2wl, MLPH, 0, acc);
    EPI_PROLOGUE();
    #pragma unroll
    for (int t = 0; t < 24; t++) {
        const int mi = t / 6, nj = t % 6;
        const int cn = wn * 48 + nj * 8 + tg * 2;
        const float b0 = fc2_b[cn], b1 = fc2_b[cn + 1];
        #pragma unroll
        for (int h = 0; h < 2; h++) {
            const int m = m0 + wm * 64 + mi * 16 + g + h * 8;
            const size_t o = (size_t)m * Cc + cn;
            float2 xs = *(const float2*)(g_x1 + o);
            *(float2*)(out + o) = make_float2(xs.x + acc[t][h * 2 + 0] + b0,
                                              xs.y + acc[t][h * 2 + 1] + b1);
        }
    }
}

// ---------------- HMMA attention: one CTA per (window, head) -------------
// Pad 49 -> 64. Scores: 3-term bf16 split QK^T. Softmax on fragments.
// PV: S c-frags reused as A-frags (P split ph+pl), V transposed in smem.
#define VSTR 144
#define ATT_SQH 0
#define ATT_SQL 5120
#define ATT_SKH 10240
#define ATT_SKL 15360
#define ATT_SVH 20480
#define ATT_SVL 25088
#define ATT_SB  29696
#define ATT_BYTES 30464

__global__ __launch_bounds__(128) void attn_kernel(
    const float* __restrict__ rpb, const float* __restrict__ gate)
{
    __shared__ __align__(16) char sm[ATT_BYTES];
    const uint32_t sb0 = smem_u32(sm);
    const int tid = threadIdx.x;
    const int wh = blockIdx.x;
    const int win = wh / NHh, head = wh - win * NHh;
    const size_t base = (size_t)wh * (Nn * HD);

    // zero all smem (pad rows/cols must be 0)
    #pragma unroll 4
    for (int i = tid; i < ATT_BYTES / 16; i += 128)
        ((uint4*)sm)[i] = make_uint4(0, 0, 0, 0);
    __syncthreads();

    // fill Q/K splits: 4 arrays x 49 rows x 4 x 16B
    for (int idx = tid; idx < 784; idx += 128) {
        const int a = idx / 196, e = idx - a * 196;
        const int r = e >> 2, p = e & 3;
        const __nv_bfloat16* src =
            ((a == 0) ? g_qh : (a == 1) ? g_ql : (a == 2) ? g_kh : g_kl)
            + base + r * 32 + p * 8;
        *(uint4*)(sm + a * 5120 + r * ASTR + p * 16) = *(const uint4*)src;
    }
    // V transposed: sVT[d][j]
    for (int idx = tid; idx < Nn * HD; idx += 128) {
        const int j = idx >> 5, d = idx & 31;
        *(__nv_bfloat16*)(sm + ATT_SVH + d * VSTR + j * 2) = g_vh[base + idx];
        *(__nv_bfloat16*)(sm + ATT_SVL + d * VSTR + j * 2) = g_vl[base + idx];
    }
    float* sbias = (float*)(sm + ATT_SB);
    for (int idx = tid; idx < 169; idx += 128) sbias[idx] = rpb[idx * NHh + head];
    __syncthreads();

    const int wid = tid >> 5, lane = tid & 31;
    const int g = lane >> 2, tg = lane & 3;
    const int lrow = lane & 15;
    const uint32_t koffh = (lane >> 4) << 4;

    // ---- scores: S[64x64] per CTA, warp owns 16 rows ----
    float sacc[8][4];
    #pragma unroll
    for (int i = 0; i < 8; i++)
        #pragma unroll
        for (int j = 0; j < 4; j++) sacc[i][j] = 0.f;

    #pragma unroll
    for (int ks = 0; ks < 2; ks++) {
        const uint32_t koff = ks * 32 + koffh;
        uint32_t qh[4], ql[4], kh[4][4], kl[4][4];
        const uint32_t qa = sb0 + ATT_SQH + (wid * 16 + lrow) * ASTR + koff;
        ldm_x4(qh, qa);
        ldm_x4(ql, qa + 5120);
        #pragma unroll
        for (int nt = 0; nt < 4; nt++) {
            const uint32_t ka = sb0 + ATT_SKH + (nt * 16 + lrow) * ASTR + koff;
            ldm_x4(kh[nt], ka);
            ldm_x4(kl[nt], ka + 5120);
        }
        #pragma unroll
        for (int nj = 0; nj < 8; nj++) {
            const uint32_t b0h = kh[nj >> 1][nj & 1], b1h = kh[nj >> 1][(nj & 1) + 2];
            const uint32_t b0l = kl[nj >> 1][nj & 1], b1l = kl[nj >> 1][(nj & 1) + 2];
            mma16816(sacc[nj], qh, b0h, b1h);
            mma16816(sacc[nj], ql, b0h, b1h);
            mma16816(sacc[nj], qh, b0l, b1l);
        }
    }

    // ---- bias + shift-mask + softmax (rows i0 = wid*16+g, i0+8) ----
    const int w_ = win & 63;
    const bool er = ((w_ >> 3) == 7), ec = ((w_ & 7) == 7);
    int prr[2], pcc[2], gii[2];
    #pragma unroll
    for (int r = 0; r < 2; r++) {
        const int ii = min(wid * 16 + g + r * 8, 48);
        prr[r] = ii / 7; pcc[r] = ii - prr[r] * 7;
        gii[r] = (er ? ((prr[r] < 4) ? 1 : 2) : 0) * 3
               + (ec ? ((pcc[r] < 4) ? 1 : 2) : 0);
    }
    float mx[2] = {-1e30f, -1e30f};
    #pragma unroll
    for (int nj = 0; nj < 8; nj++)
        #pragma unroll
        for (int e = 0; e < 4; e++) {
            const int r = e >> 1;
            const int j = nj * 8 + tg * 2 + (e & 1);
            float s;
            if (j < Nn) {
                const int rj = j / 7, cj = j - rj * 7;
                const int gj = (er ? ((rj < 4) ? 1 : 2) : 0) * 3
                             + (ec ? ((cj < 4) ? 1 : 2) : 0);
                s = sacc[nj][e] + sbias[(prr[r] - rj + 6) * 13 + (pcc[r] - cj + 6)]
                    + ((gii[r] != gj) ? -100.f : 0.f);
            } else s = -1e30f;
            sacc[nj][e] = s;
            mx[r] = fmaxf(mx[r], s);
        }
    #pragma unroll
    for (int r = 0; r < 2; r++) {
        mx[r] = fmaxf(mx[r], __shfl_xor_sync(0xffffffffu, mx[r], 1));
        mx[r] = fmaxf(mx[r], __shfl_xor_sync(0xffffffffu, mx[r], 2));
    }
    float sum[2] = {0.f, 0.f};
    #pragma unroll
    for (int nj = 0; nj < 8; nj++)
        #pragma unroll
        for (int e = 0; e < 4; e++) {
            const float p = __expf(sacc[nj][e] - mx[e >> 1]);
            sacc[nj][e] = p;
            sum[e >> 1] += p;
        }
    #pragma unroll
    for (int r = 0; r < 2; r++) {
        sum[r] += __shfl_xor_sync(0xffffffffu, sum[r], 1);
        sum[r] += __shfl_xor_sync(0xffffffffu, sum[r], 2);
    }

    // ---- pack P to bf16 split (A-frag layout == S c-frag layout) ----
    uint32_t Ph[8][2], Pl[8][2];
    #pragma unroll
    for (int nj = 0; nj < 8; nj++)
        #pragma unroll
        for (int r = 0; r < 2; r++)
            split2(sacc[nj][r * 2], sacc[nj][r * 2 + 1], Ph[nj][r], Pl[nj][r]);

    // ---- PV: O[64x32] ----
    float oacc[4][4];
    #pragma unroll
    for (int i = 0; i < 4; i++)
        #pragma unroll
        for (int j = 0; j < 4; j++) oacc[i][j] = 0.f;

    #pragma unroll
    for (int s = 0; s < 4; s++) {
        uint32_t vh[2][4], vl[2][4];
        #pragma unroll
        for (int dt = 0; dt < 2; dt++) {
            const uint32_t va = sb0 + ATT_SVH + (dt * 16 + lrow) * VSTR
                                + s * 32 + koffh;
            ldm_x4(vh[dt], va);
            ldm_x4(vl[dt], va + 4608);
        }
        uint32_t aH[4] = {Ph[2 * s][0], Ph[2 * s][1], Ph[2 * s + 1][0], Ph[2 * s + 1][1]};
        uint32_t aL[4] = {Pl[2 * s][0], Pl[2 * s][1], Pl[2 * s + 1][0], Pl[2 * s + 1][1]};
        #pragma unroll
        for (int nd = 0; nd < 4; nd++) {
            const uint32_t b0h = vh[nd >> 1][nd & 1], b1h = vh[nd >> 1][(nd & 1) + 2];
            const uint32_t b0l = vl[nd >> 1][nd & 1], b1l = vl[nd >> 1][(nd & 1) + 2];
            mma16816(oacc[nd], aH, b0h, b1h);
            mma16816(oacc[nd], aL, b0h, b1h);
            mma16816(oacc[nd], aH, b0l, b1l);
        }
    }

    // ---- scale by gate/sum, write bf16 split o ----
    const float gval = 1.f / (1.f + expf(-gate[head]));
    #pragma unroll
    for (int r = 0; r < 2; r++) {
        const int i = wid * 16 + g + r * 8;
        if (i < Nn) {
            const float inv = gval / sum[r];
            const size_t rowb = ((size_t)win * Nn + i) * Cc + head * HD;
            #pragma unroll
            for (int nd = 0; nd < 4; nd++) {
                uint32_t ph, pl;
                split2(oacc[nd][r * 2] * inv, oacc[nd][r * 2 + 1] * inv, ph, pl);
                const size_t o = rowb + nd * 8 + tg * 2;
                *(uint32_t*)(g_oh + o) = ph;
                *(uint32_t*)(g_ol + o) = pl;
            }
        }
    }
}

// ---------------- LN1 + shift + window -> bf16 split ----------------
__global__ void ln1_shift_window_kernel(const float* __restrict__ x,
                                        const float* __restrict__ g,
                                        const float* __restrict__ b)
{
    const int warp = threadIdx.x >> 5;
    const int lane = threadIdx.x & 31;
    const int t = blockIdx.x * 8 + warp;
    const int win = t / Nn;
    const int n   = t - win * Nn;
    const int bi  = win >> 6;
    const int w_  = win & 63;
    const int wr  = w_ >> 3, wc = w_ & 7;
    const int pr  = n / WS,  pc = n - (n / WS) * WS;
    int srow = wr * WS + pr + SS; if (srow >= Hh) srow -= Hh;
    int scol = wc * WS + pc + SS; if (scol >= Ww) scol -= Ww;
    const float* xp = x + ((size_t)bi * Ltok + srow * Ww + scol) * Cc;

    float v[6], s = 0.f, ss = 0.f;
    #pragma unroll
    for (int kq = 0; kq < 6; kq++) { v[kq] = xp[lane + 32 * kq]; s += v[kq]; ss += v[kq] * v[kq]; }
    #pragma unroll
    for (int off = 16; off > 0; off >>= 1) {
        s  += __shfl_xor_sync(0xffffffffu, s,  off);
        ss += __shfl_xor_sync(0xffffffffu, ss, off);
    }
    const float mean = s * (1.f / Cc);
    const float rstd = rsqrtf(ss * (1.f / Cc) - mean * mean + 1e-5f);
    #pragma unroll
    for (int kq = 0; kq < 6; kq++) {
        const int c = lane + 32 * kq;
        const float val = (v[kq] - mean) * rstd * g[c] + b[c];
        __nv_bfloat16 hi = __float2bfloat16(val);
        g_ywh[(size_t)t * Cc + c] = hi;
        g_ywl[(size_t)t * Cc + c] = __float2bfloat16(val - __bfloat162float(hi));
    }
}

// ---------------- LN2 -> bf16 split ----------------
__global__ void ln2_kernel(const float* __restrict__ g, const float* __restrict__ b)
{
    const int warp = threadIdx.x >> 5;
    const int lane = threadIdx.x & 31;
    const int t = blockIdx.x * 8 + warp;
    const float* xp = g_x1 + (size_t)t * Cc;

    float v[6], s = 0.f, ss = 0.f;
    #pragma unroll
    for (int kq = 0; kq < 6; kq++) { v[kq] = xp[lane + 32 * kq]; s += v[kq]; ss += v[kq] * v[kq]; }
    #pragma unroll
    for (int off = 16; off > 0; off >>= 1) {
        s  += __shfl_xor_sync(0xffffffffu, s,  off);
        ss += __shfl_xor_sync(0xffffffffu, ss, off);
    }
    const float mean = s * (1.f / Cc);
    const float rstd = rsqrtf(ss * (1.f / Cc) - mean * mean + 1e-5f);
    #pragma unroll
    for (int kq = 0; kq < 6; kq++) {
        const int c = lane + 32 * kq;
        const float val = (v[kq] - mean) * rstd * g[c] + b[c];
        __nv_bfloat16 hi = __float2bfloat16(val);
        g_zh[(size_t)t * Cc + c] = hi;
        g_zl[(size_t)t * Cc + c] = __float2bfloat16(val - __bfloat162float(hi));
    }
}

// ---------------- weight fp32 -> bf16 split ----------------
__global__ void split_kernel(const float* __restrict__ s,
                             __nv_bfloat16* __restrict__ h,
                             __nv_bfloat16* __restrict__ l, int n)
{
    const int i = blockIdx.x * 256 + threadIdx.x;
    if (i < n) {
        const float v = s[i];
        __nv_bfloat16 hi = __float2bfloat16(v);
        h[i] = hi;
        l[i] = __float2bfloat16(v - __bfloat162float(hi));
    }
}

// ---------------- launch ----------------
extern "C" void kernel_launch(void* const* d_in, const int* in_sizes, int n_in,
                              void* d_out, int out_size)
{
    const float* x       = (const float*)d_in[0];
    const float* norm1_g = (const float*)d_in[1];
    const float* norm1_b = (const float*)d_in[2];
    const float* qkv_w   = (const float*)d_in[3];
    const float* qkv_b   = (const float*)d_in[4];
    const float* rpb     = (const float*)d_in[5];
    const float* gate    = (const float*)d_in[6];
    const float* proj_w  = (const float*)d_in[7];
    const float* proj_b  = (const float*)d_in[8];
    const float* norm2_g = (const float*)d_in[9];
    const float* norm2_b = (const float*)d_in[10];
    const float* fc1_w   = (const float*)d_in[11];
    const float* fc1_b   = (const float*)d_in[12];
    const float* bn_g    = (const float*)d_in[13];
    const float* bn_b    = (const float*)d_in[14];
    const float* fc2_w   = (const float*)d_in[15];
    const float* fc2_b   = (const float*)d_in[16];
    float* out = (float*)d_out;

    static bool attr_done = false;
    if (!attr_done) {
        cudaFuncSetAttribute(gemm_qkv_kernel,  cudaFuncAttributeMaxDynamicSharedMemorySize, SMEM_GEMM);
        cudaFuncSetAttribute(gemm_proj_kernel, cudaFuncAttributeMaxDynamicSharedMemorySize, SMEM_GEMM);
        cudaFuncSetAttribute(gemm_fc1_kernel,  cudaFuncAttributeMaxDynamicSharedMemorySize, SMEM_GEMM);
        cudaFuncSetAttribute(gemm_fc2_kernel,  cudaFuncAttributeMaxDynamicSharedMemorySize, SMEM_GEMM);
        attr_done = true;
    }

    __nv_bfloat16 *qwh, *qwl, *pwh, *pwl, *f1h, *f1l, *f2h, *f2l;
    cudaGetSymbolAddress((void**)&qwh, g_qkvwh);  cudaGetSymbolAddress((void**)&qwl, g_qkvwl);
    cudaGetSymbolAddress((void**)&pwh, g_projwh); cudaGetSymbolAddress((void**)&pwl, g_projwl);
    cudaGetSymbolAddress((void**)&f1h, g_fc1wh);  cudaGetSymbolAddress((void**)&f1l, g_fc1wl);
    cudaGetSymbolAddress((void**)&f2h, g_fc2wh);  cudaGetSymbolAddress((void**)&f2l, g_fc2wl);

    split_kernel<<<(QKVN * Cc + 255) / 256, 256>>>(qkv_w, qwh, qwl, QKVN * Cc);
    split_kernel<<<(Cc * Cc + 255) / 256, 256>>>(proj_w, pwh, pwl, Cc * Cc);
    split_kernel<<<(MLPH * Cc + 255) / 256, 256>>>(fc1_w, f1h, f1l, MLPH * Cc);
    split_kernel<<<(Cc * MLPH + 255) / 256, 256>>>(fc2_w, f2h, f2l, Cc * MLPH);

    ln1_shift_window_kernel<<<Mrow / 8, 256>>>(x, norm1_g, norm1_b);
    gemm_qkv_kernel<<<dim3(QKVN / 192, Mrow / 128), 256, SMEM_GEMM>>>(qkv_b);
    attn_kernel<<<Bz * NW * NHh, 128>>>(rpb, gate);
    gemm_proj_kernel<<<dim3(1, Mrow / 128), 256, SMEM_GEMM>>>(proj_b, x);
    ln2_kernel<<<Mrow / 8, 256>>>(norm2_g, norm2_b);
    gemm_fc1_kernel<<<dim3(MLPH / 192, Mrow / 128), 256, SMEM_GEMM>>>(fc1_b, bn_g, bn_b);
    gemm_fc2_kernel<<<dim3(1, Mrow / 128), 256, SMEM_GEMM>>>(fc2_b, out);
}

// round 5
// speedup vs baseline: 4.0136x; 2.1425x over previous
#include <cuda_runtime.h>
#include <cuda_fp16.h>
#include <math.h>
#include <stdint.h>

// ---------------- problem constants ----------------
#define Bz    64
#define Hh    56
#define Ww    56
#define Cc    192
#define NHh   6
#define WS    7
#define SS    3
#define Nn    49
#define HD    32
#define NW    64
#define Ltok  3136
#define Mrow  200704      // B*L == 128*1568
#define MLPH  768
#define QKVN  576

// ---------------- scratch globals (fp16 single precision path) -----------
__device__ __align__(16) __half g_yw[(size_t)Mrow * Cc];
__device__ __align__(16) __half g_q [(size_t)Mrow * Cc];
__device__ __align__(16) __half g_k [(size_t)Mrow * Cc];
__device__ __align__(16) __half g_v [(size_t)Mrow * Cc];
__device__ __align__(16) __half g_o [(size_t)Mrow * Cc];
__device__ float g_x1[(size_t)Mrow * Cc];
__device__ __align__(16) __half g_z [(size_t)Mrow * Cc];
__device__ __align__(16) __half g_hh[(size_t)Mrow * MLPH];

// fp16 weights
__device__ __align__(16) __half g_qkvw[QKVN * Cc];
__device__ __align__(16) __half g_projw[Cc * Cc];
__device__ __align__(16) __half g_fc1w[MLPH * Cc];
__device__ __align__(16) __half g_fc2w[Cc * MLPH];

// ---------------- PTX helpers ----------------
__device__ __forceinline__ uint32_t smem_u32(const void* p) {
    uint32_t a;
    asm("{ .reg .u64 t; cvta.to.shared.u64 t, %1; cvt.u32.u64 %0, t; }"
        : "=r"(a) : "l"(p));
    return a;
}
__device__ __forceinline__ void cp16(uint32_t dst, const void* src) {
    asm volatile("cp.async.cg.shared.global [%0], [%1], 16;"
                 :: "r"(dst), "l"(src));
}
#define CP_COMMIT() asm volatile("cp.async.commit_group;" ::: "memory")
#define CP_WAIT2()  asm volatile("cp.async.wait_group 2;" ::: "memory")

__device__ __forceinline__ void ldm_x4(uint32_t* r, uint32_t a) {
    asm volatile("ldmatrix.sync.aligned.m8n8.x4.shared.b16 {%0,%1,%2,%3}, [%4];"
        : "=r"(r[0]), "=r"(r[1]), "=r"(r[2]), "=r"(r[3]) : "r"(a));
}
__device__ __forceinline__ void mma16816(float* d, const uint32_t* a,
                                         uint32_t b0, uint32_t b1) {
    asm volatile(
        "mma.sync.aligned.m16n8k16.row.col.f32.f16.f16.f32 "
        "{%0,%1,%2,%3}, {%4,%5,%6,%7}, {%8,%9}, {%0,%1,%2,%3};"
        : "+f"(d[0]), "+f"(d[1]), "+f"(d[2]), "+f"(d[3])
        : "r"(a[0]), "r"(a[1]), "r"(a[2]), "r"(a[3]), "r"(b0), "r"(b1));
}
__device__ __forceinline__ uint32_t pack2h(float v0, float v1) {
    __half2 h = __floats2half2_rn(v0, v1);
    return *(uint32_t*)&h;
}

// ---------------- GEMM geometry ----------------
// CTA tile 128(M) x 192(N), warps 2(m) x 4(n), warp tile 64x48.
// K-chunk 32 fp16, 4-stage cp.async pipeline. smem row stride 80B.
#define ASTR   80
#define ABYTES (128 * ASTR)     // 10240
#define BBYTES (192 * ASTR)     // 15360
#define STG    (ABYTES + BBYTES)
#define SMEM_GEMM (4 * STG)     // 102400

__device__ __forceinline__ void gemm_mma(
    const __half* __restrict__ a, const __half* __restrict__ b,
    int K, int n0, float (&acc)[24][4])
{
    extern __shared__ char sm[];
    const uint32_t sb = smem_u32(sm);
    const int tid  = threadIdx.x;
    const int wid  = tid >> 5, lane = tid & 31;
    const int wm   = wid >> 2, wn = wid & 3;
    const int m0   = blockIdx.y * 128;
    const int NCH  = K >> 5;

    #pragma unroll
    for (int i = 0; i < 24; i++)
        #pragma unroll
        for (int j = 0; j < 4; j++) acc[i][j] = 0.f;

    auto load_stage = [&](int stg, int c) {
        const __half* A = a + (size_t)m0 * K + c * 32;
        const __half* B = b + (size_t)n0 * K + c * 32;
        const uint32_t Ab = sb + (uint32_t)stg * STG;
        const uint32_t Bb = Ab + ABYTES;
        #pragma unroll
        for (int i = 0; i < 2; i++) {
            const int idx = tid + i * 256;          // 512 x 16B for A
            const int r = idx >> 2, p = idx & 3;
            cp16(Ab + r * ASTR + p * 16, A + (size_t)r * K + p * 8);
        }
        #pragma unroll
        for (int i = 0; i < 3; i++) {               // 768 x 16B for B
            const int idx = tid + i * 256;
            const int r = idx >> 2, p = idx & 3;
            cp16(Bb + r * ASTR + p * 16, B + (size_t)r * K + p * 8);
        }
    };

    load_stage(0, 0); CP_COMMIT();
    load_stage(1, 1); CP_COMMIT();
    load_stage(2, 2); CP_COMMIT();

    const uint32_t lrow  = lane & 15;
    const uint32_t koffh = (lane >> 4) << 4;   // byte offset of k-half

    for (int c = 0; c < NCH; c++) {
        CP_WAIT2();
        __syncthreads();
        const uint32_t Ab = sb + (uint32_t)(c & 3) * STG;
        const uint32_t Bb = Ab + ABYTES;
        #pragma unroll
        for (int ks = 0; ks < 2; ks++) {
            uint32_t rA[4][4], rB[3][4];
            const uint32_t koff = ks * 32 + koffh;
            #pragma unroll
            for (int mi = 0; mi < 4; mi++)
                ldm_x4(rA[mi], Ab + (wm * 64 + mi * 16 + lrow) * ASTR + koff);
            #pragma unroll
            for (int ni = 0; ni < 3; ni++)
                ldm_x4(rB[ni], Bb + (wn * 48 + ni * 16 + lrow) * ASTR + koff);
            #pragma unroll
            for (int mi = 0; mi < 4; mi++)
                #pragma unroll
                for (int nj = 0; nj < 6; nj++)
                    mma16816(acc[mi * 6 + nj], rA[mi],
                             rB[nj >> 1][nj & 1], rB[nj >> 1][(nj & 1) + 2]);
        }
        if (c + 3 < NCH) load_stage((c + 3) & 3, c + 3);
        CP_COMMIT();
    }
}

#define EPI_PROLOGUE()                                          \
    const int tid = threadIdx.x;                                \
    const int wid = tid >> 5, lane = tid & 31;                  \
    const int wm = wid >> 2, wn = wid & 3;                      \
    const int g = lane >> 2, tg = lane & 3;                     \
    const int m0 = blockIdx.y * 128;

// ---------------- QKV GEMM + scatter to fp16 q/k/v ----------------
__global__ __launch_bounds__(256) void gemm_qkv_kernel(const float* __restrict__ qkv_b)
{
    float acc[24][4];
    gemm_mma(g_yw, g_qkvw, Cc, blockIdx.x * 192, acc);
    EPI_PROLOGUE();
    const int part = blockIdx.x;  // 0:q 1:k 2:v
    __half* dst = (part == 0) ? g_q : ((part == 1) ? g_k : g_v);
    const float sc = (part == 0) ? 0.17677669529663687f : 1.0f;
    #pragma unroll
    for (int t = 0; t < 24; t++) {
        const int mi = t / 6, nj = t % 6;
        const int c = wn * 48 + nj * 8 + tg * 2;
        const float b0 = qkv_b[part * 192 + c];
        const float b1 = qkv_b[part * 192 + c + 1];
        const int head = c >> 5, d = c & 31;
        #pragma unroll
        for (int h = 0; h < 2; h++) {
            const int m = m0 + wm * 64 + mi * 16 + g + h * 8;
            const int win = m / Nn, n = m - win * Nn;
            const size_t o = ((size_t)(win * NHh + head) * Nn + n) * HD + d;
            *(uint32_t*)(dst + o) = pack2h((acc[t][h * 2 + 0] + b0) * sc,
                                           (acc[t][h * 2 + 1] + b1) * sc);
        }
    }
}

// ---------------- proj GEMM + window reverse + un-shift + residual --------
__global__ __launch_bounds__(256) void gemm_proj_kernel(
    const float* __restrict__ proj_b, const float* __restrict__ x_shortcut)
{
    float acc[24][4];
    gemm_mma(g_o, g_projw, Cc, 0, acc);
    EPI_PROLOGUE();
    #pragma unroll
    for (int t = 0; t < 24; t++) {
        const int mi = t / 6, nj = t % 6;
        const int cn = wn * 48 + nj * 8 + tg * 2;
        const float b0 = proj_b[cn], b1 = proj_b[cn + 1];
        #pragma unroll
        for (int h = 0; h < 2; h++) {
            const int m = m0 + wm * 64 + mi * 16 + g + h * 8;
            const int win = m / Nn, n = m - win * Nn;
            const int bi = win >> 6, w_ = win & 63;
            const int wr = w_ >> 3, wc = w_ & 7;
            const int pr = n / WS, pc = n - pr * WS;
            int ho = wr * WS + pr + SS; if (ho >= Hh) ho -= Hh;
            int wo = wc * WS + pc + SS; if (wo >= Ww) wo -= Ww;
            const size_t gi = ((size_t)bi * Ltok + ho * Ww + wo) * Cc + cn;
            float2 xs = *(const float2*)(x_shortcut + gi);
            *(float2*)(g_x1 + gi) = make_float2(xs.x + acc[t][h * 2 + 0] + b0,
                                                xs.y + acc[t][h * 2 + 1] + b1);
        }
    }
}

// ---------------- fc1 GEMM + BN(eval) + exact GELU -> fp16 ----------------
__global__ __launch_bounds__(256) void gemm_fc1_kernel(
    const float* __restrict__ fc1_b, const float* __restrict__ bn_g,
    const float* __restrict__ bn_b)
{
    float acc[24][4];
    gemm_mma(g_z, g_fc1w, Cc, blockIdx.x * 192, acc);
    EPI_PROLOGUE();
    const float bnscale = 0.9999950000374997f;  // 1/sqrt(1+1e-5)
    #pragma unroll
    for (int t = 0; t < 24; t++) {
        const int mi = t / 6, nj = t % 6;
        const int cn = blockIdx.x * 192 + wn * 48 + nj * 8 + tg * 2;
        const float fb0 = fc1_b[cn],  fb1 = fc1_b[cn + 1];
        const float sg0 = bnscale * bn_g[cn], sg1 = bnscale * bn_g[cn + 1];
        const float bb0 = bn_b[cn], bb1 = bn_b[cn + 1];
        #pragma unroll
        for (int h = 0; h < 2; h++) {
            const int m = m0 + wm * 64 + mi * 16 + g + h * 8;
            float v0 = (acc[t][h * 2 + 0] + fb0) * sg0 + bb0;
            float v1 = (acc[t][h * 2 + 1] + fb1) * sg1 + bb1;
            v0 = 0.5f * v0 * (1.f + erff(v0 * 0.70710678118654752f));
            v1 = 0.5f * v1 * (1.f + erff(v1 * 0.70710678118654752f));
            const size_t o = (size_t)m * MLPH + cn;
            *(uint32_t*)(g_hh + o) = pack2h(v0, v1);
        }
    }
}

// ---------------- fc2 GEMM + residual -> output ----------------
__global__ __launch_bounds__(256) void gemm_fc2_kernel(
    const float* __restrict__ fc2_b, float* __restrict__ out)
{
    float acc[24][4];
    gemm_mma(g_hh, g_fc2w, MLPH, 0, acc);
    EPI_PROLOGUE();
    #pragma unroll
    for (int t = 0; t < 24; t++) {
        const int mi = t / 6, nj = t % 6;
        const int cn = wn * 48 + nj * 8 + tg * 2;
        const float b0 = fc2_b[cn], b1 = fc2_b[cn + 1];
        #pragma unroll
        for (int h = 0; h < 2; h++) {
            const int m = m0 + wm * 64 + mi * 16 + g + h * 8;
            const size_t o = (size_t)m * Cc + cn;
            float2 xs = *(const float2*)(g_x1 + o);
            *(float2*)(out + o) = make_float2(xs.x + acc[t][h * 2 + 0] + b0,
                                              xs.y + acc[t][h * 2 + 1] + b1);
        }
    }
}

// ---------------- HMMA attention: one CTA per (window, head) -------------
#define VSTR 144
#define ATT_SQ 0
#define ATT_SK 5120
#define ATT_SV 10240
#define ATT_SB 14848
#define ATT_BYTES 15552

__global__ __launch_bounds__(128) void attn_kernel(
    const float* __restrict__ rpb, const float* __restrict__ gate)
{
    __shared__ __align__(16) char sm[ATT_BYTES];
    const uint32_t sb0 = smem_u32(sm);
    const int tid = threadIdx.x;
    const int wh = blockIdx.x;
    const int win = wh / NHh, head = wh - win * NHh;
    const size_t base = (size_t)wh * (Nn * HD);

    // zero all smem (pad rows/cols must be 0)
    #pragma unroll 4
    for (int i = tid; i < ATT_BYTES / 16; i += 128)
        ((uint4*)sm)[i] = make_uint4(0, 0, 0, 0);
    __syncthreads();

    // fill Q/K: 2 arrays x 49 rows x 4 x 16B
    for (int idx = tid; idx < 392; idx += 128) {
        const int a = idx / 196, e = idx - a * 196;
        const int r = e >> 2, p = e & 3;
        const __half* src = ((a == 0) ? g_q : g_k) + base + r * 32 + p * 8;
        *(uint4*)(sm + a * 5120 + r * ASTR + p * 16) = *(const uint4*)src;
    }
    // V transposed: sVT[d][j]
    for (int idx = tid; idx < Nn * HD; idx += 128) {
        const int j = idx >> 5, d = idx & 31;
        *(__half*)(sm + ATT_SV + d * VSTR + j * 2) = g_v[base + idx];
    }
    float* sbias = (float*)(sm + ATT_SB);
    for (int idx = tid; idx < 169; idx += 128) sbias[idx] = rpb[idx * NHh + head];
    __syncthreads();

    const int wid = tid >> 5, lane = tid & 31;
    const int g = lane >> 2, tg = lane & 3;
    const int lrow = lane & 15;
    const uint32_t koffh = (lane >> 4) << 4;

    // ---- scores: S[64x64] per CTA, warp owns 16 rows ----
    float sacc[8][4];
    #pragma unroll
    for (int i = 0; i < 8; i++)
        #pragma unroll
        for (int j = 0; j < 4; j++) sacc[i][j] = 0.f;

    #pragma unroll
    for (int ks = 0; ks < 2; ks++) {
        const uint32_t koff = ks * 32 + koffh;
        uint32_t q[4], k[4][4];
        ldm_x4(q, sb0 + ATT_SQ + (wid * 16 + lrow) * ASTR + koff);
        #pragma unroll
        for (int nt = 0; nt < 4; nt++)
            ldm_x4(k[nt], sb0 + ATT_SK + (nt * 16 + lrow) * ASTR + koff);
        #pragma unroll
        for (int nj = 0; nj < 8; nj++)
            mma16816(sacc[nj], q, k[nj >> 1][nj & 1], k[nj >> 1][(nj & 1) + 2]);
    }

    // ---- bias + shift-mask + softmax (rows i0 = wid*16+g, i0+8) ----
    const int w_ = win & 63;
    const bool er = ((w_ >> 3) == 7), ec = ((w_ & 7) == 7);
    int prr[2], pcc[2], gii[2];
    #pragma unroll
    for (int r = 0; r < 2; r++) {
        const int ii = min(wid * 16 + g + r * 8, 48);
        prr[r] = ii / 7; pcc[r] = ii - prr[r] * 7;
        gii[r] = (er ? ((prr[r] < 4) ? 1 : 2) : 0) * 3
               + (ec ? ((pcc[r] < 4) ? 1 : 2) : 0);
    }
    float mx[2] = {-1e30f, -1e30f};
    #pragma unroll
    for (int nj = 0; nj < 8; nj++)
        #pragma unroll
        for (int e = 0; e < 4; e++) {
            const int r = e >> 1;
            const int j = nj * 8 + tg * 2 + (e & 1);
            float s;
            if (j < Nn) {
                const int rj = j / 7, cj = j - rj * 7;
                const int gj = (er ? ((rj < 4) ? 1 : 2) : 0) * 3
                             + (ec ? ((cj < 4) ? 1 : 2) : 0);
                s = sacc[nj][e] + sbias[(prr[r] - rj + 6) * 13 + (pcc[r] - cj + 6)]
                    + ((gii[r] != gj) ? -100.f : 0.f);
            } else s = -1e30f;
            sacc[nj][e] = s;
            mx[r] = fmaxf(mx[r], s);
        }
    #pragma unroll
    for (int r = 0; r < 2; r++) {
        mx[r] = fmaxf(mx[r], __shfl_xor_sync(0xffffffffu, mx[r], 1));
        mx[r] = fmaxf(mx[r], __shfl_xor_sync(0xffffffffu, mx[r], 2));
    }
    float sum[2] = {0.f, 0.f};
    #pragma unroll
    for (int nj = 0; nj < 8; nj++)
        #pragma unroll
        for (int e = 0; e < 4; e++) {
            const float p = __expf(sacc[nj][e] - mx[e >> 1]);
            sacc[nj][e] = p;
            sum[e >> 1] += p;
        }
    #pragma unroll
    for (int r = 0; r < 2; r++) {
        sum[r] += __shfl_xor_sync(0xffffffffu, sum[r], 1);
        sum[r] += __shfl_xor_sync(0xffffffffu, sum[r], 2);
    }

    // ---- pack P to fp16 (A-frag layout == S c-frag layout) ----
    uint32_t Ph[8][2];
    #pragma unroll
    for (int nj = 0; nj < 8; nj++)
        #pragma unroll
        for (int r = 0; r < 2; r++)
            Ph[nj][r] = pack2h(sacc[nj][r * 2], sacc[nj][r * 2 + 1]);

    // ---- PV: O[64x32] ----
    float oacc[4][4];
    #pragma unroll
    for (int i = 0; i < 4; i++)
        #pragma unroll
        for (int j = 0; j < 4; j++) oacc[i][j] = 0.f;

    #pragma unroll
    for (int s = 0; s < 4; s++) {
        uint32_t vv[2][4];
        #pragma unroll
        for (int dt = 0; dt < 2; dt++)
            ldm_x4(vv[dt], sb0 + ATT_SV + (dt * 16 + lrow) * VSTR + s * 32 + koffh);
        uint32_t aH[4] = {Ph[2 * s][0], Ph[2 * s][1], Ph[2 * s + 1][0], Ph[2 * s + 1][1]};
        #pragma unroll
        for (int nd = 0; nd < 4; nd++)
            mma16816(oacc[nd], aH, vv[nd >> 1][nd & 1], vv[nd >> 1][(nd & 1) + 2]);
    }

    // ---- scale by gate/sum, write fp16 o ----
    const float gval = 1.f / (1.f + expf(-gate[head]));
    #pragma unroll
    for (int r = 0; r < 2; r++) {
        const int i = wid * 16 + g + r * 8;
        if (i < Nn) {
            const float inv = gval / sum[r];
            const size_t rowb = ((size_t)win * Nn + i) * Cc + head * HD;
            #pragma unroll
            for (int nd = 0; nd < 4; nd++) {
                const size_t o = rowb + nd * 8 + tg * 2;
                *(uint32_t*)(g_o + o) = pack2h(oacc[nd][r * 2] * inv,
                                               oacc[nd][r * 2 + 1] * inv);
            }
        }
    }
}

// ---------------- LN1 + shift + window -> fp16 ----------------
__global__ void ln1_shift_window_kernel(const float* __restrict__ x,
                                        const float* __restrict__ g,
                                        const float* __restrict__ b)
{
    const int warp = threadIdx.x >> 5;
    const int lane = threadIdx.x & 31;
    const int t = blockIdx.x * 8 + warp;
    const int win = t / Nn;
    const int n   = t - win * Nn;
    const int bi  = win >> 6;
    const int w_  = win & 63;
    const int wr  = w_ >> 3, wc = w_ & 7;
    const int pr  = n / WS,  pc = n - (n / WS) * WS;
    int srow = wr * WS + pr + SS; if (srow >= Hh) srow -= Hh;
    int scol = wc * WS + pc + SS; if (scol >= Ww) scol -= Ww;
    const float* xp = x + ((size_t)bi * Ltok + srow * Ww + scol) * Cc;

    float v[6], s = 0.f, ss = 0.f;
    #pragma unroll
    for (int kq = 0; kq < 6; kq++) { v[kq] = xp[lane + 32 * kq]; s += v[kq]; ss += v[kq] * v[kq]; }
    #pragma unroll
    for (int off = 16; off > 0; off >>= 1) {
        s  += __shfl_xor_sync(0xffffffffu, s,  off);
        ss += __shfl_xor_sync(0xffffffffu, ss, off);
    }
    const float mean = s * (1.f / Cc);
    const float rstd = rsqrtf(ss * (1.f / Cc) - mean * mean + 1e-5f);
    #pragma unroll
    for (int kq = 0; kq < 6; kq++) {
        const int c = lane + 32 * kq;
        g_yw[(size_t)t * Cc + c] = __float2half((v[kq] - mean) * rstd * g[c] + b[c]);
    }
}

// ---------------- LN2 -> fp16 ----------------
__global__ void ln2_kernel(const float* __restrict__ g, const float* __restrict__ b)
{
    const int warp = threadIdx.x >> 5;
    const int lane = threadIdx.x & 31;
    const int t = blockIdx.x * 8 + warp;
    const float* xp = g_x1 + (size_t)t * Cc;

    float v[6], s = 0.f, ss = 0.f;
    #pragma unroll
    for (int kq = 0; kq < 6; kq++) { v[kq] = xp[lane + 32 * kq]; s += v[kq]; ss += v[kq] * v[kq]; }
    #pragma unroll
    for (int off = 16; off > 0; off >>= 1) {
        s  += __shfl_xor_sync(0xffffffffu, s,  off);
        ss += __shfl_xor_sync(0xffffffffu, ss, off);
    }
    const float mean = s * (1.f / Cc);
    const float rstd = rsqrtf(ss * (1.f / Cc) - mean * mean + 1e-5f);
    #pragma unroll
    for (int kq = 0; kq < 6; kq++) {
        const int c = lane + 32 * kq;
        g_z[(size_t)t * Cc + c] = __float2half((v[kq] - mean) * rstd * g[c] + b[c]);
    }
}

// ---------------- weight fp32 -> fp16 ----------------
__global__ void cvt_kernel(const float* __restrict__ s,
                           __half* __restrict__ h, int n)
{
    const int i = blockIdx.x * 256 + threadIdx.x;
    if (i < n) h[i] = __float2half(s[i]);
}

// ---------------- launch ----------------
extern "C" void kernel_launch(void* const* d_in, const int* in_sizes, int n_in,
                              void* d_out, int out_size)
{
    const float* x       = (const float*)d_in[0];
    const float* norm1_g = (const float*)d_in[1];
    const float* norm1_b = (const float*)d_in[2];
    const float* qkv_w   = (const float*)d_in[3];
    const float* qkv_b   = (const float*)d_in[4];
    const float* rpb     = (const float*)d_in[5];
    const float* gate    = (const float*)d_in[6];
    const float* proj_w  = (const float*)d_in[7];
    const float* proj_b  = (const float*)d_in[8];
    const float* norm2_g = (const float*)d_in[9];
    const float* norm2_b = (const float*)d_in[10];
    const float* fc1_w   = (const float*)d_in[11];
    const float* fc1_b   = (const float*)d_in[12];
    const float* bn_g    = (const float*)d_in[13];
    const float* bn_b    = (const float*)d_in[14];
    const float* fc2_w   = (const float*)d_in[15];
    const float* fc2_b   = (const float*)d_in[16];
    float* out = (float*)d_out;

    static bool attr_done = false;
    if (!attr_done) {
        cudaFuncSetAttribute(gemm_qkv_kernel,  cudaFuncAttributeMaxDynamicSharedMemorySize, SMEM_GEMM);
        cudaFuncSetAttribute(gemm_proj_kernel, cudaFuncAttributeMaxDynamicSharedMemorySize, SMEM_GEMM);
        cudaFuncSetAttribute(gemm_fc1_kernel,  cudaFuncAttributeMaxDynamicSharedMemorySize, SMEM_GEMM);
        cudaFuncSetAttribute(gemm_fc2_kernel,  cudaFuncAttributeMaxDynamicSharedMemorySize, SMEM_GEMM);
        attr_done = true;
    }

    __half *qw, *pw, *f1, *f2;
    cudaGetSymbolAddress((void**)&qw, g_qkvw);
    cudaGetSymbolAddress((void**)&pw, g_projw);
    cudaGetSymbolAddress((void**)&f1, g_fc1w);
    cudaGetSymbolAddress((void**)&f2, g_fc2w);

    cvt_kernel<<<(QKVN * Cc + 255) / 256, 256>>>(qkv_w, qw, QKVN * Cc);
    cvt_kernel<<<(Cc * Cc + 255) / 256, 256>>>(proj_w, pw, Cc * Cc);
    cvt_kernel<<<(MLPH * Cc + 255) / 256, 256>>>(fc1_w, f1, MLPH * Cc);
    cvt_kernel<<<(Cc * MLPH + 255) / 256, 256>>>(fc2_w, f2, Cc * MLPH);

    ln1_shift_window_kernel<<<Mrow / 8, 256>>>(x, norm1_g, norm1_b);
    gemm_qkv_kernel<<<dim3(QKVN / 192, Mrow / 128), 256, SMEM_GEMM>>>(qkv_b);
    attn_kernel<<<Bz * NW * NHh, 128>>>(rpb, gate);
    gemm_proj_kernel<<<dim3(1, Mrow / 128), 256, SMEM_GEMM>>>(proj_b, x);
    ln2_kernel<<<Mrow / 8, 256>>>(norm2_g, norm2_b);
    gemm_fc1_kernel<<<dim3(MLPH / 192, Mrow / 128), 256, SMEM_GEMM>>>(fc1_b, bn_g, bn_b);
    gemm_fc2_kernel<<<dim3(1, Mrow / 128), 256, SMEM_GEMM>>>(fc2_b, out);
}

// round 7
// speedup vs baseline: 4.1523x; 1.0346x over previous
#include <cuda_runtime.h>
#include <cuda_fp16.h>
#include <math.h>
#include <stdint.h>

// ---------------- problem constants ----------------
#define Bz    64
#define Hh    56
#define Ww    56
#define Cc    192
#define NHh   6
#define WS    7
#define SS    3
#define Nn    49
#define HD    32
#define NW    64
#define Ltok  3136
#define Mrow  200704      // B*L == 128*1568
#define MLPH  768
#define QKVN  576

// ---------------- scratch globals ----------------
__device__ __align__(16) __half g_yw[(size_t)Mrow * Cc];
__device__ __align__(16) __half g_q [(size_t)Mrow * Cc];
__device__ __align__(16) __half g_k [(size_t)Mrow * Cc];
__device__ __align__(16) __half g_v [(size_t)Mrow * Cc];
__device__ __align__(16) __half g_o [(size_t)Mrow * Cc];
__device__ float g_x1[(size_t)Mrow * Cc];
__device__ __align__(16) __half g_z [(size_t)Mrow * Cc];   // SPATIAL row order
__device__ __align__(16) __half g_hh[(size_t)Mrow * MLPH];

// fp16 weights
__device__ __align__(16) __half g_qkvw[QKVN * Cc];
__device__ __align__(16) __half g_projw[Cc * Cc];
__device__ __align__(16) __half g_fc1w[MLPH * Cc];
__device__ __align__(16) __half g_fc2w[Cc * MLPH];

// ---------------- PTX helpers ----------------
__device__ __forceinline__ uint32_t smem_u32(const void* p) {
    uint32_t a;
    asm("{ .reg .u64 t; cvta.to.shared.u64 t, %1; cvt.u32.u64 %0, t; }"
        : "=r"(a) : "l"(p));
    return a;
}
__device__ __forceinline__ void cp16(uint32_t dst, const void* src) {
    asm volatile("cp.async.cg.shared.global [%0], [%1], 16;"
                 :: "r"(dst), "l"(src));
}
#define CP_COMMIT() asm volatile("cp.async.commit_group;" ::: "memory")
#define CP_WAIT2()  asm volatile("cp.async.wait_group 2;" ::: "memory")
#define CP_WAIT0()  asm volatile("cp.async.wait_group 0;" ::: "memory")

__device__ __forceinline__ void ldm_x4(uint32_t* r, uint32_t a) {
    asm volatile("ldmatrix.sync.aligned.m8n8.x4.shared.b16 {%0,%1,%2,%3}, [%4];"
        : "=r"(r[0]), "=r"(r[1]), "=r"(r[2]), "=r"(r[3]) : "r"(a));
}
__device__ __forceinline__ void ldm_x4t(uint32_t* r, uint32_t a) {
    asm volatile("ldmatrix.sync.aligned.m8n8.x4.trans.shared.b16 {%0,%1,%2,%3}, [%4];"
        : "=r"(r[0]), "=r"(r[1]), "=r"(r[2]), "=r"(r[3]) : "r"(a));
}
__device__ __forceinline__ void mma16816(float* d, const uint32_t* a,
                                         uint32_t b0, uint32_t b1) {
    asm volatile(
        "mma.sync.aligned.m16n8k16.row.col.f32.f16.f16.f32 "
        "{%0,%1,%2,%3}, {%4,%5,%6,%7}, {%8,%9}, {%0,%1,%2,%3};"
        : "+f"(d[0]), "+f"(d[1]), "+f"(d[2]), "+f"(d[3])
        : "r"(a[0]), "r"(a[1]), "r"(a[2]), "r"(a[3]), "r"(b0), "r"(b1));
}
__device__ __forceinline__ uint32_t pack2h(float v0, float v1) {
    __half2 h = __floats2half2_rn(v0, v1);
    return *(uint32_t*)&h;
}

// ---------------- GEMM geometry ----------------
#define ASTR   80
#define ABYTES (128 * ASTR)
#define BBYTES (192 * ASTR)
#define STG    (ABYTES + BBYTES)
#define SMEM_GEMM (4 * STG)     // 102400 (>= 98304 for fp32 epi staging)

__device__ __forceinline__ void gemm_mma(
    const __half* __restrict__ a, const __half* __restrict__ b,
    int K, int n0, float (&acc)[24][4])
{
    extern __shared__ char sm[];
    const uint32_t sb = smem_u32(sm);
    const int tid  = threadIdx.x;
    const int wid  = tid >> 5, lane = tid & 31;
    const int wm   = wid >> 2, wn = wid & 3;
    const int m0   = blockIdx.y * 128;
    const int NCH  = K >> 5;

    #pragma unroll
    for (int i = 0; i < 24; i++)
        #pragma unroll
        for (int j = 0; j < 4; j++) acc[i][j] = 0.f;

    auto load_stage = [&](int stg, int c) {
        const __half* A = a + (size_t)m0 * K + c * 32;
        const __half* B = b + (size_t)n0 * K + c * 32;
        const uint32_t Ab = sb + (uint32_t)stg * STG;
        const uint32_t Bb = Ab + ABYTES;
        #pragma unroll
        for (int i = 0; i < 2; i++) {
            const int idx = tid + i * 256;
            const int r = idx >> 2, p = idx & 3;
            cp16(Ab + r * ASTR + p * 16, A + (size_t)r * K + p * 8);
        }
        #pragma unroll
        for (int i = 0; i < 3; i++) {
            const int idx = tid + i * 256;
            const int r = idx >> 2, p = idx & 3;
            cp16(Bb + r * ASTR + p * 16, B + (size_t)r * K + p * 8);
        }
    };

    load_stage(0, 0); CP_COMMIT();
    load_stage(1, 1); CP_COMMIT();
    load_stage(2, 2); CP_COMMIT();

    const uint32_t lrow  = lane & 15;
    const uint32_t koffh = (lane >> 4) << 4;

    for (int c = 0; c < NCH; c++) {
        CP_WAIT2();
        __syncthreads();
        const uint32_t Ab = sb + (uint32_t)(c & 3) * STG;
        const uint32_t Bb = Ab + ABYTES;
        #pragma unroll
        for (int ks = 0; ks < 2; ks++) {
            uint32_t rA[4][4], rB[3][4];
            const uint32_t koff = ks * 32 + koffh;
            #pragma unroll
            for (int mi = 0; mi < 4; mi++)
                ldm_x4(rA[mi], Ab + (wm * 64 + mi * 16 + lrow) * ASTR + koff);
            #pragma unroll
            for (int ni = 0; ni < 3; ni++)
                ldm_x4(rB[ni], Bb + (wn * 48 + ni * 16 + lrow) * ASTR + koff);
            #pragma unroll
            for (int mi = 0; mi < 4; mi++)
                #pragma unroll
                for (int nj = 0; nj < 6; nj++)
                    mma16816(acc[mi * 6 + nj], rA[mi],
                             rB[nj >> 1][nj & 1], rB[nj >> 1][(nj & 1) + 2]);
        }
        if (c + 3 < NCH) load_stage((c + 3) & 3, c + 3);
        CP_COMMIT();
    }
    CP_WAIT0();
    __syncthreads();   // smem free for epilogue staging
}

#define EPI_PROLOGUE()                                          \
    extern __shared__ char sm[];                                \
    const int tid = threadIdx.x;                                \
    const int wid = tid >> 5, lane = tid & 31;                  \
    const int wm = wid >> 2, wn = wid & 3;                      \
    const int g = lane >> 2, tg = lane & 3;                     \
    const int m0 = blockIdx.y * 128;

// ---------------- QKV GEMM + coalesced scatter to fp16 q/k/v -------------
__global__ __launch_bounds__(256) void gemm_qkv_kernel(const float* __restrict__ qkv_b)
{
    float acc[24][4];
    gemm_mma(g_yw, g_qkvw, Cc, blockIdx.x * 192, acc);
    EPI_PROLOGUE();
    const int part = blockIdx.x;  // 0:q 1:k 2:v
    __half* dst = (part == 0) ? g_q : ((part == 1) ? g_k : g_v);
    const float sc = (part == 0) ? 0.17677669529663687f : 1.0f;
    __half* sh = (__half*)sm;   // [128][192]
    #pragma unroll
    for (int t = 0; t < 24; t++) {
        const int mi = t / 6, nj = t % 6;
        const int c = wn * 48 + nj * 8 + tg * 2;
        const float b0 = qkv_b[part * 192 + c];
        const float b1 = qkv_b[part * 192 + c + 1];
        #pragma unroll
        for (int h = 0; h < 2; h++) {
            const int r = wm * 64 + mi * 16 + g + h * 8;
            *(uint32_t*)(sh + r * 192 + c) =
                pack2h((acc[t][h * 2 + 0] + b0) * sc, (acc[t][h * 2 + 1] + b1) * sc);
        }
    }
    __syncthreads();
    #pragma unroll
    for (int i = 0; i < 12; i++) {
        const int idx = tid + i * 256;        // 3072 = 128 rows x 24 segs
        const int r = idx / 24, s = idx - r * 24;
        const int head = s >> 2, d = (s & 3) * 8;
        const int m = m0 + r;
        const int win = m / Nn, n = m - win * Nn;
        const uint4 v = *(const uint4*)(sh + r * 192 + s * 8);
        *(uint4*)(dst + ((size_t)(win * NHh + head) * Nn + n) * HD + d) = v;
    }
}

// ---------------- proj GEMM + residual + FUSED LN2 ----------------
__global__ __launch_bounds__(256) void gemm_proj_kernel(
    const float* __restrict__ proj_b, const float* __restrict__ x_shortcut,
    const float* __restrict__ norm2_g, const float* __restrict__ norm2_b)
{
    float acc[24][4];
    gemm_mma(g_o, g_projw, Cc, 0, acc);
    EPI_PROLOGUE();
    float* sh = (float*)sm;    // [128][192] proj_out + bias
    #pragma unroll
    for (int t = 0; t < 24; t++) {
        const int mi = t / 6, nj = t % 6;
        const int cn = wn * 48 + nj * 8 + tg * 2;
        const float b0 = proj_b[cn], b1 = proj_b[cn + 1];
        #pragma unroll
        for (int h = 0; h < 2; h++) {
            const int r = wm * 64 + mi * 16 + g + h * 8;
            *(float2*)(sh + r * 192 + cn) =
                make_float2(acc[t][h * 2 + 0] + b0, acc[t][h * 2 + 1] + b1);
        }
    }
    __syncthreads();
    // warp-per-row: x read (coalesced) + residual -> x1, LN -> z
    // x1 AND z are both written at the SPATIAL row (gidx) so the MLP
    // (fc1/fc2) and the final residual share one consistent row ordering.
    float gg[6], bb[6];
    #pragma unroll
    for (int i = 0; i < 6; i++) {
        gg[i] = norm2_g[lane * 6 + i];
        bb[i] = norm2_b[lane * 6 + i];
    }
    for (int r = wid; r < 128; r += 8) {
        const int m = m0 + r;
        const int win = m / Nn, n = m - win * Nn;
        const int bi = win >> 6, w_ = win & 63;
        const int wr = w_ >> 3, wc = w_ & 7;
        const int pr = n / WS, pc = n - pr * WS;
        int ho = wr * WS + pr + SS; if (ho >= Hh) ho -= Hh;
        int wo = wc * WS + pc + SS; if (wo >= Ww) wo -= Ww;
        const size_t gidx = ((size_t)bi * Ltok + ho * Ww + wo) * Cc;

        float v[6];
        const float* xr = x_shortcut + gidx + lane * 6;
        const float* sr = sh + r * 192 + lane * 6;
        float2 t0 = *(const float2*)(xr);
        float2 t1 = *(const float2*)(xr + 2);
        float2 t2 = *(const float2*)(xr + 4);
        v[0] = t0.x + sr[0]; v[1] = t0.y + sr[1];
        v[2] = t1.x + sr[2]; v[3] = t1.y + sr[3];
        v[4] = t2.x + sr[4]; v[5] = t2.y + sr[5];

        float s = 0.f, ss = 0.f;
        #pragma unroll
        for (int i = 0; i < 6; i++) { s += v[i]; ss += v[i] * v[i]; }
        #pragma unroll
        for (int off = 16; off > 0; off >>= 1) {
            s  += __shfl_xor_sync(0xffffffffu, s,  off);
            ss += __shfl_xor_sync(0xffffffffu, ss, off);
        }
        const float mean = s * (1.f / Cc);
        const float rstd = rsqrtf(ss * (1.f / Cc) - mean * mean + 1e-5f);

        float* x1r = g_x1 + gidx + lane * 6;
        *(float2*)(x1r)     = make_float2(v[0], v[1]);
        *(float2*)(x1r + 2) = make_float2(v[2], v[3]);
        *(float2*)(x1r + 4) = make_float2(v[4], v[5]);

        __half* zr = g_z + gidx + lane * 6;   // FIXED: spatial order
        *(uint32_t*)(zr)     = pack2h((v[0]-mean)*rstd*gg[0]+bb[0], (v[1]-mean)*rstd*gg[1]+bb[1]);
        *(uint32_t*)(zr + 2) = pack2h((v[2]-mean)*rstd*gg[2]+bb[2], (v[3]-mean)*rstd*gg[3]+bb[3]);
        *(uint32_t*)(zr + 4) = pack2h((v[4]-mean)*rstd*gg[4]+bb[4], (v[5]-mean)*rstd*gg[5]+bb[5]);
    }
}

// ---------------- fc1 GEMM + BN(eval) + exact GELU -> fp16 (coalesced) ----
__global__ __launch_bounds__(256) void gemm_fc1_kernel(
    const float* __restrict__ fc1_b, const float* __restrict__ bn_g,
    const float* __restrict__ bn_b)
{
    float acc[24][4];
    const int n0 = blockIdx.x * 192;
    gemm_mma(g_z, g_fc1w, Cc, n0, acc);
    EPI_PROLOGUE();
    const float bnscale = 0.9999950000374997f;  // 1/sqrt(1+1e-5)
    __half* sh = (__half*)sm;   // [128][192]
    #pragma unroll
    for (int t = 0; t < 24; t++) {
        const int mi = t / 6, nj = t % 6;
        const int c = wn * 48 + nj * 8 + tg * 2;
        const int cn = n0 + c;
        const float fb0 = fc1_b[cn],  fb1 = fc1_b[cn + 1];
        const float sg0 = bnscale * bn_g[cn], sg1 = bnscale * bn_g[cn + 1];
        const float bb0 = bn_b[cn], bb1 = bn_b[cn + 1];
        #pragma unroll
        for (int h = 0; h < 2; h++) {
            const int r = wm * 64 + mi * 16 + g + h * 8;
            float v0 = (acc[t][h * 2 + 0] + fb0) * sg0 + bb0;
            float v1 = (acc[t][h * 2 + 1] + fb1) * sg1 + bb1;
            v0 = 0.5f * v0 * (1.f + erff(v0 * 0.70710678118654752f));
            v1 = 0.5f * v1 * (1.f + erff(v1 * 0.70710678118654752f));
            *(uint32_t*)(sh + r * 192 + c) = pack2h(v0, v1);
        }
    }
    __syncthreads();
    #pragma unroll
    for (int i = 0; i < 12; i++) {
        const int idx = tid + i * 256;
        const int r = idx / 24, s = idx - r * 24;
        const uint4 v = *(const uint4*)(sh + r * 192 + s * 8);
        *(uint4*)(g_hh + (size_t)(m0 + r) * MLPH + n0 + s * 8) = v;
    }
}

// ---------------- fc2 GEMM + residual -> output (coalesced) ---------------
__global__ __launch_bounds__(256) void gemm_fc2_kernel(
    const float* __restrict__ fc2_b, float* __restrict__ out)
{
    float acc[24][4];
    gemm_mma(g_hh, g_fc2w, MLPH, 0, acc);
    EPI_PROLOGUE();
    float* sh = (float*)sm;    // [128][192]
    #pragma unroll
    for (int t = 0; t < 24; t++) {
        const int mi = t / 6, nj = t % 6;
        const int cn = wn * 48 + nj * 8 + tg * 2;
        const float b0 = fc2_b[cn], b1 = fc2_b[cn + 1];
        #pragma unroll
        for (int h = 0; h < 2; h++) {
            const int r = wm * 64 + mi * 16 + g + h * 8;
            *(float2*)(sh + r * 192 + cn) =
                make_float2(acc[t][h * 2 + 0] + b0, acc[t][h * 2 + 1] + b1);
        }
    }
    __syncthreads();
    #pragma unroll
    for (int i = 0; i < 24; i++) {
        const int idx = tid + i * 256;        // 6144 float4
        const int r = idx / 48, q = idx - r * 48;
        const size_t o = (size_t)(m0 + r) * Cc + q * 4;
        float4 sv = *(const float4*)(sh + r * 192 + q * 4);
        float4 xv = *(const float4*)(g_x1 + o);
        *(float4*)(out + o) = make_float4(xv.x + sv.x, xv.y + sv.y,
                                          xv.z + sv.z, xv.w + sv.w);
    }
}

// ---------------- HMMA attention: one CTA per (window, head) -------------
#define ATT_SQ 0
#define ATT_SK 5120
#define ATT_SV 10240
#define ATT_SB 15360
#define ATT_BYTES 16064

__global__ __launch_bounds__(128) void attn_kernel(
    const float* __restrict__ rpb, const float* __restrict__ gate)
{
    __shared__ __align__(16) char sm[ATT_BYTES];
    const uint32_t sb0 = smem_u32(sm);
    const int tid = threadIdx.x;
    const int wh = blockIdx.x;
    const int win = wh / NHh, head = wh - win * NHh;
    const size_t base = (size_t)wh * (Nn * HD);

    // fill Q/K rows 0-48 (pad rows stay garbage: only reach masked score
    // columns (overwritten with -1e30) or discarded output rows)
    for (int idx = tid; idx < 392; idx += 128) {
        const int a = idx / 196, e = idx - a * 196;
        const int r = e >> 2, p = e & 3;
        const __half* src = ((a == 0) ? g_q : g_k) + base + r * 32 + p * 8;
        *(uint4*)(sm + a * 5120 + r * ASTR + p * 16) = *(const uint4*)src;
    }
    // fill V rows 0-48, zero pad rows 49-63 (P pad cols are exp(-1e30)=0
    // but 0*NaN would poison valid outputs, so V pads must be finite)
    for (int idx = tid; idx < 196; idx += 128) {
        const int r = idx >> 2, p = idx & 3;
        *(uint4*)(sm + ATT_SV + r * ASTR + p * 16) =
            *(const uint4*)(g_v + base + r * 32 + p * 8);
    }
    if (tid < 60) {
        const int r = 49 + (tid >> 2), p = tid & 3;
        *(uint4*)(sm + ATT_SV + r * ASTR + p * 16) = make_uint4(0, 0, 0, 0);
    }
    float* sbias = (float*)(sm + ATT_SB);
    for (int idx = tid; idx < 169; idx += 128) sbias[idx] = rpb[idx * NHh + head];
    __syncthreads();

    const int wid = tid >> 5, lane = tid & 31;
    const int g = lane >> 2, tg = lane & 3;
    const int lrow = lane & 15;
    const uint32_t koffh = (lane >> 4) << 4;

    // ---- scores: S[64x64], warp owns 16 rows ----
    float sacc[8][4];
    #pragma unroll
    for (int i = 0; i < 8; i++)
        #pragma unroll
        for (int j = 0; j < 4; j++) sacc[i][j] = 0.f;

    #pragma unroll
    for (int ks = 0; ks < 2; ks++) {
        const uint32_t koff = ks * 32 + koffh;
        uint32_t q[4], k[4][4];
        ldm_x4(q, sb0 + ATT_SQ + (wid * 16 + lrow) * ASTR + koff);
        #pragma unroll
        for (int nt = 0; nt < 4; nt++)
            ldm_x4(k[nt], sb0 + ATT_SK + (nt * 16 + lrow) * ASTR + koff);
        #pragma unroll
        for (int nj = 0; nj < 8; nj++)
            mma16816(sacc[nj], q, k[nj >> 1][nj & 1], k[nj >> 1][(nj & 1) + 2]);
    }

    // ---- bias + shift-mask + softmax ----
    const int w_ = win & 63;
    const bool er = ((w_ >> 3) == 7), ec = ((w_ & 7) == 7);
    int prr[2], pcc[2], gii[2];
    #pragma unroll
    for (int r = 0; r < 2; r++) {
        const int ii = min(wid * 16 + g + r * 8, 48);
        prr[r] = ii / 7; pcc[r] = ii - prr[r] * 7;
        gii[r] = (er ? ((prr[r] < 4) ? 1 : 2) : 0) * 3
               + (ec ? ((pcc[r] < 4) ? 1 : 2) : 0);
    }
    float mx[2] = {-1e30f, -1e30f};
    #pragma unroll
    for (int nj = 0; nj < 8; nj++)
        #pragma unroll
        for (int e = 0; e < 4; e++) {
            const int r = e >> 1;
            const int j = nj * 8 + tg * 2 + (e & 1);
            float s;
            if (j < Nn) {
                const int rj = j / 7, cj = j - rj * 7;
                const int gj = (er ? ((rj < 4) ? 1 : 2) : 0) * 3
                             + (ec ? ((cj < 4) ? 1 : 2) : 0);
                s = sacc[nj][e] + sbias[(prr[r] - rj + 6) * 13 + (pcc[r] - cj + 6)]
                    + ((gii[r] != gj) ? -100.f : 0.f);
            } else s = -1e30f;
            sacc[nj][e] = s;
            mx[r] = fmaxf(mx[r], s);
        }
    #pragma unroll
    for (int r = 0; r < 2; r++) {
        mx[r] = fmaxf(mx[r], __shfl_xor_sync(0xffffffffu, mx[r], 1));
        mx[r] = fmaxf(mx[r], __shfl_xor_sync(0xffffffffu, mx[r], 2));
    }
    float sum[2] = {0.f, 0.f};
    #pragma unroll
    for (int nj = 0; nj < 8; nj++)
        #pragma unroll
        for (int e = 0; e < 4; e++) {
            const float p = __expf(sacc[nj][e] - mx[e >> 1]);
            sacc[nj][e] = p;
            sum[e >> 1] += p;
        }
    #pragma unroll
    for (int r = 0; r < 2; r++) {
        sum[r] += __shfl_xor_sync(0xffffffffu, sum[r], 1);
        sum[r] += __shfl_xor_sync(0xffffffffu, sum[r], 2);
    }

    // ---- pack P to fp16 (A-frag layout == S c-frag layout) ----
    uint32_t Ph[8][2];
    #pragma unroll
    for (int nj = 0; nj < 8; nj++)
        #pragma unroll
        for (int r = 0; r < 2; r++)
            Ph[nj][r] = pack2h(sacc[nj][r * 2], sacc[nj][r * 2 + 1]);

    // ---- PV: O[64x32], V[j][d] row-major via ldmatrix.trans ----
    float oacc[4][4];
    #pragma unroll
    for (int i = 0; i < 4; i++)
        #pragma unroll
        for (int j = 0; j < 4; j++) oacc[i][j] = 0.f;

    #pragma unroll
    for (int s = 0; s < 4; s++) {
        uint32_t v0[4], v1[4];
        const uint32_t va = sb0 + ATT_SV + (s * 16 + (lane & 15)) * ASTR
                            + ((lane >> 4) << 4);
        ldm_x4t(v0, va);        // d 0-15
        ldm_x4t(v1, va + 32);   // d 16-31
        uint32_t aH[4] = {Ph[2*s][0], Ph[2*s][1], Ph[2*s+1][0], Ph[2*s+1][1]};
        mma16816(oacc[0], aH, v0[0], v0[1]);
        mma16816(oacc[1], aH, v0[2], v0[3]);
        mma16816(oacc[2], aH, v1[0], v1[1]);
        mma16816(oacc[3], aH, v1[2], v1[3]);
    }

    // ---- scale by gate/sum, write fp16 o ----
    const float gval = 1.f / (1.f + expf(-gate[head]));
    #pragma unroll
    for (int r = 0; r < 2; r++) {
        const int i = wid * 16 + g + r * 8;
        if (i < Nn) {
            const float inv = gval / sum[r];
            const size_t rowb = ((size_t)win * Nn + i) * Cc + head * HD;
            #pragma unroll
            for (int nd = 0; nd < 4; nd++) {
                const size_t o = rowb + nd * 8 + tg * 2;
                *(uint32_t*)(g_o + o) = pack2h(oacc[nd][r * 2] * inv,
                                               oacc[nd][r * 2 + 1] * inv);
            }
        }
    }
}

// ---------------- LN1 + shift + window -> fp16 ----------------
__global__ void ln1_shift_window_kernel(const float* __restrict__ x,
                                        const float* __restrict__ g,
                                        const float* __restrict__ b)
{
    const int warp = threadIdx.x >> 5;
    const int lane = threadIdx.x & 31;
    const int t = blockIdx.x * 8 + warp;
    const int win = t / Nn;
    const int n   = t - win * Nn;
    const int bi  = win >> 6;
    const int w_  = win & 63;
    const int wr  = w_ >> 3, wc = w_ & 7;
    const int pr  = n / WS,  pc = n - (n / WS) * WS;
    int srow = wr * WS + pr + SS; if (srow >= Hh) srow -= Hh;
    int scol = wc * WS + pc + SS; if (scol >= Ww) scol -= Ww;
    const float* xp = x + ((size_t)bi * Ltok + srow * Ww + scol) * Cc;

    float v[6], s = 0.f, ss = 0.f;
    #pragma unroll
    for (int kq = 0; kq < 6; kq++) { v[kq] = xp[lane + 32 * kq]; s += v[kq]; ss += v[kq] * v[kq]; }
    #pragma unroll
    for (int off = 16; off > 0; off >>= 1) {
        s  += __shfl_xor_sync(0xffffffffu, s,  off);
        ss += __shfl_xor_sync(0xffffffffu, ss, off);
    }
    const float mean = s * (1.f / Cc);
    const float rstd = rsqrtf(ss * (1.f / Cc) - mean * mean + 1e-5f);
    #pragma unroll
    for (int kq = 0; kq < 6; kq++) {
        const int c = lane + 32 * kq;
        g_yw[(size_t)t * Cc + c] = __float2half((v[kq] - mean) * rstd * g[c] + b[c]);
    }
}

// ---------------- weight fp32 -> fp16 ----------------
__global__ void cvt_kernel(const float* __restrict__ s,
                           __half* __restrict__ h, int n)
{
    const int i = blockIdx.x * 256 + threadIdx.x;
    if (i < n) h[i] = __float2half(s[i]);
}

// ---------------- launch ----------------
extern "C" void kernel_launch(void* const* d_in, const int* in_sizes, int n_in,
                              void* d_out, int out_size)
{
    const float* x       = (const float*)d_in[0];
    const float* norm1_g = (const float*)d_in[1];
    const float* norm1_b = (const float*)d_in[2];
    const float* qkv_w   = (const float*)d_in[3];
    const float* qkv_b   = (const float*)d_in[4];
    const float* rpb     = (const float*)d_in[5];
    const float* gate    = (const float*)d_in[6];
    const float* proj_w  = (const float*)d_in[7];
    const float* proj_b  = (const float*)d_in[8];
    const float* norm2_g = (const float*)d_in[9];
    const float* norm2_b = (const float*)d_in[10];
    const float* fc1_w   = (const float*)d_in[11];
    const float* fc1_b   = (const float*)d_in[12];
    const float* bn_g    = (const float*)d_in[13];
    const float* bn_b    = (const float*)d_in[14];
    const float* fc2_w   = (const float*)d_in[15];
    const float* fc2_b   = (const float*)d_in[16];
    float* out = (float*)d_out;

    static bool attr_done = false;
    if (!attr_done) {
        cudaFuncSetAttribute(gemm_qkv_kernel,  cudaFuncAttributeMaxDynamicSharedMemorySize, SMEM_GEMM);
        cudaFuncSetAttribute(gemm_proj_kernel, cudaFuncAttributeMaxDynamicSharedMemorySize, SMEM_GEMM);
        cudaFuncSetAttribute(gemm_fc1_kernel,  cudaFuncAttributeMaxDynamicSharedMemorySize, SMEM_GEMM);
        cudaFuncSetAttribute(gemm_fc2_kernel,  cudaFuncAttributeMaxDynamicSharedMemorySize, SMEM_GEMM);
        attr_done = true;
    }

    __half *qw, *pw, *f1, *f2;
    cudaGetSymbolAddress((void**)&qw, g_qkvw);
    cudaGetSymbolAddress((void**)&pw, g_projw);
    cudaGetSymbolAddress((void**)&f1, g_fc1w);
    cudaGetSymbolAddress((void**)&f2, g_fc2w);

    cvt_kernel<<<(QKVN * Cc + 255) / 256, 256>>>(qkv_w, qw, QKVN * Cc);
    cvt_kernel<<<(Cc * Cc + 255) / 256, 256>>>(proj_w, pw, Cc * Cc);
    cvt_kernel<<<(MLPH * Cc + 255) / 256, 256>>>(fc1_w, f1, MLPH * Cc);
    cvt_kernel<<<(Cc * MLPH + 255) / 256, 256>>>(fc2_w, f2, Cc * MLPH);

    ln1_shift_window_kernel<<<Mrow / 8, 256>>>(x, norm1_g, norm1_b);
    gemm_qkv_kernel<<<dim3(QKVN / 192, Mrow / 128), 256, SMEM_GEMM>>>(qkv_b);
    attn_kernel<<<Bz * NW * NHh, 128>>>(rpb, gate);
    gemm_proj_kernel<<<dim3(1, Mrow / 128), 256, SMEM_GEMM>>>(proj_b, x, norm2_g, norm2_b);
    gemm_fc1_kernel<<<dim3(MLPH / 192, Mrow / 128), 256, SMEM_GEMM>>>(fc1_b, bn_g, bn_b);
    gemm_fc2_kernel<<<dim3(1, Mrow / 128), 256, SMEM_GEMM>>>(fc2_b, out);
}

// round 8
// speedup vs baseline: 4.3897x; 1.0572x over previous
#include <cuda_runtime.h>
#include <cuda_fp16.h>
#include <math.h>
#include <stdint.h>

// ---------------- problem constants ----------------
#define Bz    64
#define Hh    56
#define Ww    56
#define Cc    192
#define NHh   6
#define WS    7
#define SS    3
#define Nn    49
#define HD    32
#define NW    64
#define Ltok  3136
#define Mrow  200704      // B*L == 128*1568
#define MLPH  768
#define QKVN  576

// ---------------- scratch globals ----------------
__device__ __align__(16) __half g_yw[(size_t)Mrow * Cc];
__device__ __align__(16) __half g_q [(size_t)Mrow * Cc];
__device__ __align__(16) __half g_k [(size_t)Mrow * Cc];
__device__ __align__(16) __half g_v [(size_t)Mrow * Cc];
__device__ __align__(16) __half g_o [(size_t)Mrow * Cc];
__device__ float g_x1[(size_t)Mrow * Cc];
__device__ __align__(16) __half g_z [(size_t)Mrow * Cc];   // SPATIAL row order
__device__ __align__(16) __half g_hh[(size_t)Mrow * MLPH];

// fp16 weights
__device__ __align__(16) __half g_qkvw[QKVN * Cc];
__device__ __align__(16) __half g_projw[Cc * Cc];
__device__ __align__(16) __half g_fc1w[MLPH * Cc];
__device__ __align__(16) __half g_fc2w[Cc * MLPH];

// ---------------- PTX helpers ----------------
__device__ __forceinline__ uint32_t smem_u32(const void* p) {
    uint32_t a;
    asm("{ .reg .u64 t; cvta.to.shared.u64 t, %1; cvt.u32.u64 %0, t; }"
        : "=r"(a) : "l"(p));
    return a;
}
__device__ __forceinline__ void cp16(uint32_t dst, const void* src) {
    asm volatile("cp.async.cg.shared.global [%0], [%1], 16;"
                 :: "r"(dst), "l"(src));
}
#define CP_COMMIT() asm volatile("cp.async.commit_group;" ::: "memory")
#define CP_WAIT1()  asm volatile("cp.async.wait_group 1;" ::: "memory")
#define CP_WAIT0()  asm volatile("cp.async.wait_group 0;" ::: "memory")

__device__ __forceinline__ void ldm_x4(uint32_t* r, uint32_t a) {
    asm volatile("ldmatrix.sync.aligned.m8n8.x4.shared.b16 {%0,%1,%2,%3}, [%4];"
        : "=r"(r[0]), "=r"(r[1]), "=r"(r[2]), "=r"(r[3]) : "r"(a));
}
__device__ __forceinline__ void ldm_x4t(uint32_t* r, uint32_t a) {
    asm volatile("ldmatrix.sync.aligned.m8n8.x4.trans.shared.b16 {%0,%1,%2,%3}, [%4];"
        : "=r"(r[0]), "=r"(r[1]), "=r"(r[2]), "=r"(r[3]) : "r"(a));
}
__device__ __forceinline__ void mma16816(float* d, const uint32_t* a,
                                         uint32_t b0, uint32_t b1) {
    asm volatile(
        "mma.sync.aligned.m16n8k16.row.col.f32.f16.f16.f32 "
        "{%0,%1,%2,%3}, {%4,%5,%6,%7}, {%8,%9}, {%0,%1,%2,%3};"
        : "+f"(d[0]), "+f"(d[1]), "+f"(d[2]), "+f"(d[3])
        : "r"(a[0]), "r"(a[1]), "r"(a[2]), "r"(a[3]), "r"(b0), "r"(b1));
}
__device__ __forceinline__ uint32_t pack2h(float v0, float v1) {
    __half2 h = __floats2half2_rn(v0, v1);
    return *(uint32_t*)&h;
}

// ---------------- GEMM geometry ----------------
// CTA tile 128(M) x 192(N), warps 2(m) x 4(n), warp tile 64x48.
// K-chunk 64 fp16 = 128B rows, XOR-swizzled (col' = col ^ (row&7)):
// conflict-free for both cp.async STS and ldmatrix. 3-stage pipeline.
#define GA_BYTES (128 * 128)     // 16384
#define GB_BYTES (192 * 128)     // 24576
#define GSTG     (GA_BYTES + GB_BYTES)
#define SMEM_GEMM (3 * GSTG)     // 122880 (>= 98304 for fp32 epi staging)

// attention keeps its own 80B-row layout
#define ASTR   80

__device__ __forceinline__ void gemm_mma(
    const __half* __restrict__ a, const __half* __restrict__ b,
    int K, int n0, float (&acc)[24][4])
{
    extern __shared__ char sm[];
    const uint32_t sb = smem_u32(sm);
    const int tid  = threadIdx.x;
    const int wid  = tid >> 5, lane = tid & 31;
    const int wm   = wid >> 2, wn = wid & 3;
    const int m0   = blockIdx.y * 128;
    const int NCH  = K >> 6;

    #pragma unroll
    for (int i = 0; i < 24; i++)
        #pragma unroll
        for (int j = 0; j < 4; j++) acc[i][j] = 0.f;

    auto load_stage = [&](int stg, int c) {
        const __half* A = a + (size_t)m0 * K + c * 64;
        const __half* B = b + (size_t)n0 * K + c * 64;
        const uint32_t Ab = sb + (uint32_t)stg * GSTG;
        const uint32_t Bb = Ab + GA_BYTES;
        #pragma unroll
        for (int i = 0; i < 4; i++) {              // A: 1024 x 16B
            const int idx = tid + i * 256;
            const int r = idx >> 3, p = idx & 7;
            cp16(Ab + r * 128 + ((p ^ (r & 7)) << 4), A + (size_t)r * K + p * 8);
        }
        #pragma unroll
        for (int i = 0; i < 6; i++) {              // B: 1536 x 16B
            const int idx = tid + i * 256;
            const int r = idx >> 3, p = idx & 7;
            cp16(Bb + r * 128 + ((p ^ (r & 7)) << 4), B + (size_t)r * K + p * 8);
        }
    };

    load_stage(0, 0); CP_COMMIT();
    load_stage(1, 1); CP_COMMIT();

    const int lrow  = lane & 15;
    const int chalf = lane >> 4;     // 16B col half-select

    for (int c = 0; c < NCH; c++) {
        if (c < NCH - 1) { CP_WAIT1(); } else { CP_WAIT0(); }
        __syncthreads();
        const uint32_t Ab = sb + (uint32_t)(c % 3) * GSTG;
        const uint32_t Bb = Ab + GA_BYTES;
        #pragma unroll
        for (int ks = 0; ks < 4; ks++) {
            const int col = ks * 2 + chalf;        // 16B col index 0..7
            uint32_t rA[4][4], rB[3][4];
            #pragma unroll
            for (int mi = 0; mi < 4; mi++) {
                const int row = wm * 64 + mi * 16 + lrow;
                ldm_x4(rA[mi], Ab + row * 128 + ((col ^ (row & 7)) << 4));
            }
            #pragma unroll
            for (int ni = 0; ni < 3; ni++) {
                const int row = wn * 48 + ni * 16 + lrow;
                ldm_x4(rB[ni], Bb + row * 128 + ((col ^ (row & 7)) << 4));
            }
            #pragma unroll
            for (int mi = 0; mi < 4; mi++)
                #pragma unroll
                for (int nj = 0; nj < 6; nj++)
                    mma16816(acc[mi * 6 + nj], rA[mi],
                             rB[nj >> 1][nj & 1], rB[nj >> 1][(nj & 1) + 2]);
        }
        if (c + 2 < NCH) { load_stage((c + 2) % 3, c + 2); CP_COMMIT(); }
    }
    __syncthreads();   // smem free for epilogue staging
}

#define EPI_PROLOGUE()                                          \
    extern __shared__ char sm[];                                \
    const int tid = threadIdx.x;                                \
    const int wid = tid >> 5, lane = tid & 31;                  \
    const int wm = wid >> 2, wn = wid & 3;                      \
    const int g = lane >> 2, tg = lane & 3;                     \
    const int m0 = blockIdx.y * 128;

// ---------------- QKV GEMM + coalesced scatter to fp16 q/k/v -------------
__global__ __launch_bounds__(256) void gemm_qkv_kernel(const float* __restrict__ qkv_b)
{
    float acc[24][4];
    gemm_mma(g_yw, g_qkvw, Cc, blockIdx.x * 192, acc);
    EPI_PROLOGUE();
    const int part = blockIdx.x;  // 0:q 1:k 2:v
    __half* dst = (part == 0) ? g_q : ((part == 1) ? g_k : g_v);
    const float sc = (part == 0) ? 0.17677669529663687f : 1.0f;
    __half* sh = (__half*)sm;   // [128][192]
    #pragma unroll
    for (int t = 0; t < 24; t++) {
        const int mi = t / 6, nj = t % 6;
        const int c = wn * 48 + nj * 8 + tg * 2;
        const float b0 = qkv_b[part * 192 + c];
        const float b1 = qkv_b[part * 192 + c + 1];
        #pragma unroll
        for (int h = 0; h < 2; h++) {
            const int r = wm * 64 + mi * 16 + g + h * 8;
            *(uint32_t*)(sh + r * 192 + c) =
                pack2h((acc[t][h * 2 + 0] + b0) * sc, (acc[t][h * 2 + 1] + b1) * sc);
        }
    }
    __syncthreads();
    #pragma unroll
    for (int i = 0; i < 12; i++) {
        const int idx = tid + i * 256;        // 3072 = 128 rows x 24 segs
        const int r = idx / 24, s = idx - r * 24;
        const int head = s >> 2, d = (s & 3) * 8;
        const int m = m0 + r;
        const int win = m / Nn, n = m - win * Nn;
        const uint4 v = *(const uint4*)(sh + r * 192 + s * 8);
        *(uint4*)(dst + ((size_t)(win * NHh + head) * Nn + n) * HD + d) = v;
    }
}

// ---------------- proj GEMM + residual + FUSED LN2 ----------------
__global__ __launch_bounds__(256) void gemm_proj_kernel(
    const float* __restrict__ proj_b, const float* __restrict__ x_shortcut,
    const float* __restrict__ norm2_g, const float* __restrict__ norm2_b)
{
    float acc[24][4];
    gemm_mma(g_o, g_projw, Cc, 0, acc);
    EPI_PROLOGUE();
    float* sh = (float*)sm;    // [128][192] proj_out + bias
    #pragma unroll
    for (int t = 0; t < 24; t++) {
        const int mi = t / 6, nj = t % 6;
        const int cn = wn * 48 + nj * 8 + tg * 2;
        const float b0 = proj_b[cn], b1 = proj_b[cn + 1];
        #pragma unroll
        for (int h = 0; h < 2; h++) {
            const int r = wm * 64 + mi * 16 + g + h * 8;
            *(float2*)(sh + r * 192 + cn) =
                make_float2(acc[t][h * 2 + 0] + b0, acc[t][h * 2 + 1] + b1);
        }
    }
    __syncthreads();
    // warp-per-row: residual -> x1, LN -> z (both in SPATIAL row order)
    float gg[6], bb[6];
    #pragma unroll
    for (int i = 0; i < 6; i++) {
        gg[i] = norm2_g[lane * 6 + i];
        bb[i] = norm2_b[lane * 6 + i];
    }
    for (int r = wid; r < 128; r += 8) {
        const int m = m0 + r;
        const int win = m / Nn, n = m - win * Nn;
        const int bi = win >> 6, w_ = win & 63;
        const int wr = w_ >> 3, wc = w_ & 7;
        const int pr = n / WS, pc = n - pr * WS;
        int ho = wr * WS + pr + SS; if (ho >= Hh) ho -= Hh;
        int wo = wc * WS + pc + SS; if (wo >= Ww) wo -= Ww;
        const size_t gidx = ((size_t)bi * Ltok + ho * Ww + wo) * Cc;

        float v[6];
        const float* xr = x_shortcut + gidx + lane * 6;
        const float* sr = sh + r * 192 + lane * 6;
        float2 t0 = *(const float2*)(xr);
        float2 t1 = *(const float2*)(xr + 2);
        float2 t2 = *(const float2*)(xr + 4);
        v[0] = t0.x + sr[0]; v[1] = t0.y + sr[1];
        v[2] = t1.x + sr[2]; v[3] = t1.y + sr[3];
        v[4] = t2.x + sr[4]; v[5] = t2.y + sr[5];

        float s = 0.f, ss = 0.f;
        #pragma unroll
        for (int i = 0; i < 6; i++) { s += v[i]; ss += v[i] * v[i]; }
        #pragma unroll
        for (int off = 16; off > 0; off >>= 1) {
            s  += __shfl_xor_sync(0xffffffffu, s,  off);
            ss += __shfl_xor_sync(0xffffffffu, ss, off);
        }
        const float mean = s * (1.f / Cc);
        const float rstd = rsqrtf(ss * (1.f / Cc) - mean * mean + 1e-5f);

        float* x1r = g_x1 + gidx + lane * 6;
        *(float2*)(x1r)     = make_float2(v[0], v[1]);
        *(float2*)(x1r + 2) = make_float2(v[2], v[3]);
        *(float2*)(x1r + 4) = make_float2(v[4], v[5]);

        __half* zr = g_z + gidx + lane * 6;   // spatial order
        *(uint32_t*)(zr)     = pack2h((v[0]-mean)*rstd*gg[0]+bb[0], (v[1]-mean)*rstd*gg[1]+bb[1]);
        *(uint32_t*)(zr + 2) = pack2h((v[2]-mean)*rstd*gg[2]+bb[2], (v[3]-mean)*rstd*gg[3]+bb[3]);
        *(uint32_t*)(zr + 4) = pack2h((v[4]-mean)*rstd*gg[4]+bb[4], (v[5]-mean)*rstd*gg[5]+bb[5]);
    }
}

// ---------------- fc1 GEMM + BN(eval) + exact GELU -> fp16 (coalesced) ----
__global__ __launch_bounds__(256) void gemm_fc1_kernel(
    const float* __restrict__ fc1_b, const float* __restrict__ bn_g,
    const float* __restrict__ bn_b)
{
    float acc[24][4];
    const int n0 = blockIdx.x * 192;
    gemm_mma(g_z, g_fc1w, Cc, n0, acc);
    EPI_PROLOGUE();
    const float bnscale = 0.9999950000374997f;  // 1/sqrt(1+1e-5)
    __half* sh = (__half*)sm;   // [128][192]
    #pragma unroll
    for (int t = 0; t < 24; t++) {
        const int mi = t / 6, nj = t % 6;
        const int c = wn * 48 + nj * 8 + tg * 2;
        const int cn = n0 + c;
        const float fb0 = fc1_b[cn],  fb1 = fc1_b[cn + 1];
        const float sg0 = bnscale * bn_g[cn], sg1 = bnscale * bn_g[cn + 1];
        const float bb0 = bn_b[cn], bb1 = bn_b[cn + 1];
        #pragma unroll
        for (int h = 0; h < 2; h++) {
            const int r = wm * 64 + mi * 16 + g + h * 8;
            float v0 = (acc[t][h * 2 + 0] + fb0) * sg0 + bb0;
            float v1 = (acc[t][h * 2 + 1] + fb1) * sg1 + bb1;
            v0 = 0.5f * v0 * (1.f + erff(v0 * 0.70710678118654752f));
            v1 = 0.5f * v1 * (1.f + erff(v1 * 0.70710678118654752f));
            *(uint32_t*)(sh + r * 192 + c) = pack2h(v0, v1);
        }
    }
    __syncthreads();
    #pragma unroll
    for (int i = 0; i < 12; i++) {
        const int idx = tid + i * 256;
        const int r = idx / 24, s = idx - r * 24;
        const uint4 v = *(const uint4*)(sh + r * 192 + s * 8);
        *(uint4*)(g_hh + (size_t)(m0 + r) * MLPH + n0 + s * 8) = v;
    }
}

// ---------------- fc2 GEMM + residual -> output (coalesced) ---------------
__global__ __launch_bounds__(256) void gemm_fc2_kernel(
    const float* __restrict__ fc2_b, float* __restrict__ out)
{
    float acc[24][4];
    gemm_mma(g_hh, g_fc2w, MLPH, 0, acc);
    EPI_PROLOGUE();
    float* sh = (float*)sm;    // [128][192]
    #pragma unroll
    for (int t = 0; t < 24; t++) {
        const int mi = t / 6, nj = t % 6;
        const int cn = wn * 48 + nj * 8 + tg * 2;
        const float b0 = fc2_b[cn], b1 = fc2_b[cn + 1];
        #pragma unroll
        for (int h = 0; h < 2; h++) {
            const int r = wm * 64 + mi * 16 + g + h * 8;
            *(float2*)(sh + r * 192 + cn) =
                make_float2(acc[t][h * 2 + 0] + b0, acc[t][h * 2 + 1] + b1);
        }
    }
    __syncthreads();
    #pragma unroll
    for (int i = 0; i < 24; i++) {
        const int idx = tid + i * 256;        // 6144 float4
        const int r = idx / 48, q = idx - r * 48;
        const size_t o = (size_t)(m0 + r) * Cc + q * 4;
        float4 sv = *(const float4*)(sh + r * 192 + q * 4);
        float4 xv = *(const float4*)(g_x1 + o);
        *(float4*)(out + o) = make_float4(xv.x + sv.x, xv.y + sv.y,
                                          xv.z + sv.z, xv.w + sv.w);
    }
}

// ---------------- HMMA attention: one CTA per (window, head) -------------
#define ATT_SQ 0
#define ATT_SK 5120
#define ATT_SV 10240
#define ATT_SB 15360
#define ATT_BYTES 16064

__global__ __launch_bounds__(128) void attn_kernel(
    const float* __restrict__ rpb, const float* __restrict__ gate)
{
    __shared__ __align__(16) char sm[ATT_BYTES];
    const uint32_t sb0 = smem_u32(sm);
    const int tid = threadIdx.x;
    const int wh = blockIdx.x;
    const int win = wh / NHh, head = wh - win * NHh;
    const size_t base = (size_t)wh * (Nn * HD);

    // fill Q/K rows 0-48 (pad rows: garbage only reaches masked/discarded)
    for (int idx = tid; idx < 392; idx += 128) {
        const int a = idx / 196, e = idx - a * 196;
        const int r = e >> 2, p = e & 3;
        const __half* src = ((a == 0) ? g_q : g_k) + base + r * 32 + p * 8;
        *(uint4*)(sm + a * 5120 + r * ASTR + p * 16) = *(const uint4*)src;
    }
    // fill V rows 0-48, zero pad rows 49-63
    for (int idx = tid; idx < 196; idx += 128) {
        const int r = idx >> 2, p = idx & 3;
        *(uint4*)(sm + ATT_SV + r * ASTR + p * 16) =
            *(const uint4*)(g_v + base + r * 32 + p * 8);
    }
    if (tid < 60) {
        const int r = 49 + (tid >> 2), p = tid & 3;
        *(uint4*)(sm + ATT_SV + r * ASTR + p * 16) = make_uint4(0, 0, 0, 0);
    }
    float* sbias = (float*)(sm + ATT_SB);
    for (int idx = tid; idx < 169; idx += 128) sbias[idx] = rpb[idx * NHh + head];
    __syncthreads();

    const int wid = tid >> 5, lane = tid & 31;
    const int g = lane >> 2, tg = lane & 3;
    const int lrow = lane & 15;
    const uint32_t koffh = (lane >> 4) << 4;

    // ---- scores: S[64x64], warp owns 16 rows ----
    float sacc[8][4];
    #pragma unroll
    for (int i = 0; i < 8; i++)
        #pragma unroll
        for (int j = 0; j < 4; j++) sacc[i][j] = 0.f;

    #pragma unroll
    for (int ks = 0; ks < 2; ks++) {
        const uint32_t koff = ks * 32 + koffh;
        uint32_t q[4], k[4][4];
        ldm_x4(q, sb0 + ATT_SQ + (wid * 16 + lrow) * ASTR + koff);
        #pragma unroll
        for (int nt = 0; nt < 4; nt++)
            ldm_x4(k[nt], sb0 + ATT_SK + (nt * 16 + lrow) * ASTR + koff);
        #pragma unroll
        for (int nj = 0; nj < 8; nj++)
            mma16816(sacc[nj], q, k[nj >> 1][nj & 1], k[nj >> 1][(nj & 1) + 2]);
    }

    // ---- bias + shift-mask + softmax ----
    const int w_ = win & 63;
    const bool er = ((w_ >> 3) == 7), ec = ((w_ & 7) == 7);
    int prr[2], pcc[2], gii[2];
    #pragma unroll
    for (int r = 0; r < 2; r++) {
        const int ii = min(wid * 16 + g + r * 8, 48);
        prr[r] = ii / 7; pcc[r] = ii - prr[r] * 7;
        gii[r] = (er ? ((prr[r] < 4) ? 1 : 2) : 0) * 3
               + (ec ? ((pcc[r] < 4) ? 1 : 2) : 0);
    }
    float mx[2] = {-1e30f, -1e30f};
    #pragma unroll
    for (int nj = 0; nj < 8; nj++)
        #pragma unroll
        for (int e = 0; e < 4; e++) {
            const int r = e >> 1;
            const int j = nj * 8 + tg * 2 + (e & 1);
            float s;
            if (j < Nn) {
                const int rj = j / 7, cj = j - rj * 7;
                const int gj = (er ? ((rj < 4) ? 1 : 2) : 0) * 3
                             + (ec ? ((cj < 4) ? 1 : 2) : 0);
                s = sacc[nj][e] + sbias[(prr[r] - rj + 6) * 13 + (pcc[r] - cj + 6)]
                    + ((gii[r] != gj) ? -100.f : 0.f);
            } else s = -1e30f;
            sacc[nj][e] = s;
            mx[r] = fmaxf(mx[r], s);
        }
    #pragma unroll
    for (int r = 0; r < 2; r++) {
        mx[r] = fmaxf(mx[r], __shfl_xor_sync(0xffffffffu, mx[r], 1));
        mx[r] = fmaxf(mx[r], __shfl_xor_sync(0xffffffffu, mx[r], 2));
    }
    float sum[2] = {0.f, 0.f};
    #pragma unroll
    for (int nj = 0; nj < 8; nj++)
        #pragma unroll
        for (int e = 0; e < 4; e++) {
            const float p = __expf(sacc[nj][e] - mx[e >> 1]);
            sacc[nj][e] = p;
            sum[e >> 1] += p;
        }
    #pragma unroll
    for (int r = 0; r < 2; r++) {
        sum[r] += __shfl_xor_sync(0xffffffffu, sum[r], 1);
        sum[r] += __shfl_xor_sync(0xffffffffu, sum[r], 2);
    }

    // ---- pack P to fp16 ----
    uint32_t Ph[8][2];
    #pragma unroll
    for (int nj = 0; nj < 8; nj++)
        #pragma unroll
        for (int r = 0; r < 2; r++)
            Ph[nj][r] = pack2h(sacc[nj][r * 2], sacc[nj][r * 2 + 1]);

    // ---- PV: O[64x32], V row-major via ldmatrix.trans ----
    float oacc[4][4];
    #pragma unroll
    for (int i = 0; i < 4; i++)
        #pragma unroll
        for (int j = 0; j < 4; j++) oacc[i][j] = 0.f;

    #pragma unroll
    for (int s = 0; s < 4; s++) {
        uint32_t v0[4], v1[4];
        const uint32_t va = sb0 + ATT_SV + (s * 16 + (lane & 15)) * ASTR
                            + ((lane >> 4) << 4);
        ldm_x4t(v0, va);        // d 0-15
        ldm_x4t(v1, va + 32);   // d 16-31
        uint32_t aH[4] = {Ph[2*s][0], Ph[2*s][1], Ph[2*s+1][0], Ph[2*s+1][1]};
        mma16816(oacc[0], aH, v0[0], v0[1]);
        mma16816(oacc[1], aH, v0[2], v0[3]);
        mma16816(oacc[2], aH, v1[0], v1[1]);
        mma16816(oacc[3], aH, v1[2], v1[3]);
    }

    // ---- scale by gate/sum, write fp16 o ----
    const float gval = 1.f / (1.f + expf(-gate[head]));
    #pragma unroll
    for (int r = 0; r < 2; r++) {
        const int i = wid * 16 + g + r * 8;
        if (i < Nn) {
            const float inv = gval / sum[r];
            const size_t rowb = ((size_t)win * Nn + i) * Cc + head * HD;
            #pragma unroll
            for (int nd = 0; nd < 4; nd++) {
                const size_t o = rowb + nd * 8 + tg * 2;
                *(uint32_t*)(g_o + o) = pack2h(oacc[nd][r * 2] * inv,
                                               oacc[nd][r * 2 + 1] * inv);
            }
        }
    }
}

// ---------------- LN1 + shift + window -> fp16 ----------------
__global__ void ln1_shift_window_kernel(const float* __restrict__ x,
                                        const float* __restrict__ g,
                                        const float* __restrict__ b)
{
    const int warp = threadIdx.x >> 5;
    const int lane = threadIdx.x & 31;
    const int t = blockIdx.x * 8 + warp;
    const int win = t / Nn;
    const int n   = t - win * Nn;
    const int bi  = win >> 6;
    const int w_  = win & 63;
    const int wr  = w_ >> 3, wc = w_ & 7;
    const int pr  = n / WS,  pc = n - (n / WS) * WS;
    int srow = wr * WS + pr + SS; if (srow >= Hh) srow -= Hh;
    int scol = wc * WS + pc + SS; if (scol >= Ww) scol -= Ww;
    const float* xp = x + ((size_t)bi * Ltok + srow * Ww + scol) * Cc;

    float v[6], s = 0.f, ss = 0.f;
    #pragma unroll
    for (int kq = 0; kq < 6; kq++) { v[kq] = xp[lane + 32 * kq]; s += v[kq]; ss += v[kq] * v[kq]; }
    #pragma unroll
    for (int off = 16; off > 0; off >>= 1) {
        s  += __shfl_xor_sync(0xffffffffu, s,  off);
        ss += __shfl_xor_sync(0xffffffffu, ss, off);
    }
    const float mean = s * (1.f / Cc);
    const float rstd = rsqrtf(ss * (1.f / Cc) - mean * mean + 1e-5f);
    #pragma unroll
    for (int kq = 0; kq < 6; kq++) {
        const int c = lane + 32 * kq;
        g_yw[(size_t)t * Cc + c] = __float2half((v[kq] - mean) * rstd * g[c] + b[c]);
    }
}

// ---------------- weight fp32 -> fp16 ----------------
__global__ void cvt_kernel(const float* __restrict__ s,
                           __half* __restrict__ h, int n)
{
    const int i = blockIdx.x * 256 + threadIdx.x;
    if (i < n) h[i] = __float2half(s[i]);
}

// ---------------- launch ----------------
extern "C" void kernel_launch(void* const* d_in, const int* in_sizes, int n_in,
                              void* d_out, int out_size)
{
    const float* x       = (const float*)d_in[0];
    const float* norm1_g = (const float*)d_in[1];
    const float* norm1_b = (const float*)d_in[2];
    const float* qkv_w   = (const float*)d_in[3];
    const float* qkv_b   = (const float*)d_in[4];
    const float* rpb     = (const float*)d_in[5];
    const float* gate    = (const float*)d_in[6];
    const float* proj_w  = (const float*)d_in[7];
    const float* proj_b  = (const float*)d_in[8];
    const float* norm2_g = (const float*)d_in[9];
    const float* norm2_b = (const float*)d_in[10];
    const float* fc1_w   = (const float*)d_in[11];
    const float* fc1_b   = (const float*)d_in[12];
    const float* bn_g    = (const float*)d_in[13];
    const float* bn_b    = (const float*)d_in[14];
    const float* fc2_w   = (const float*)d_in[15];
    const float* fc2_b   = (const float*)d_in[16];
    float* out = (float*)d_out;

    static bool attr_done = false;
    if (!attr_done) {
        cudaFuncSetAttribute(gemm_qkv_kernel,  cudaFuncAttributeMaxDynamicSharedMemorySize, SMEM_GEMM);
        cudaFuncSetAttribute(gemm_proj_kernel, cudaFuncAttributeMaxDynamicSharedMemorySize, SMEM_GEMM);
        cudaFuncSetAttribute(gemm_fc1_kernel,  cudaFuncAttributeMaxDynamicSharedMemorySize, SMEM_GEMM);
        cudaFuncSetAttribute(gemm_fc2_kernel,  cudaFuncAttributeMaxDynamicSharedMemorySize, SMEM_GEMM);
        attr_done = true;
    }

    __half *qw, *pw, *f1, *f2;
    cudaGetSymbolAddress((void**)&qw, g_qkvw);
    cudaGetSymbolAddress((void**)&pw, g_projw);
    cudaGetSymbolAddress((void**)&f1, g_fc1w);
    cudaGetSymbolAddress((void**)&f2, g_fc2w);

    cvt_kernel<<<(QKVN * Cc + 255) / 256, 256>>>(qkv_w, qw, QKVN * Cc);
    cvt_kernel<<<(Cc * Cc + 255) / 256, 256>>>(proj_w, pw, Cc * Cc);
    cvt_kernel<<<(MLPH * Cc + 255) / 256, 256>>>(fc1_w, f1, MLPH * Cc);
    cvt_kernel<<<(Cc * MLPH + 255) / 256, 256>>>(fc2_w, f2, Cc * MLPH);

    ln1_shift_window_kernel<<<Mrow / 8, 256>>>(x, norm1_g, norm1_b);
    gemm_qkv_kernel<<<dim3(QKVN / 192, Mrow / 128), 256, SMEM_GEMM>>>(qkv_b);
    attn_kernel<<<Bz * NW * NHh, 128>>>(rpb, gate);
    gemm_proj_kernel<<<dim3(1, Mrow / 128), 256, SMEM_GEMM>>>(proj_b, x, norm2_g, norm2_b);
    gemm_fc1_kernel<<<dim3(MLPH / 192, Mrow / 128), 256, SMEM_GEMM>>>(fc1_b, bn_g, bn_b);
    gemm_fc2_kernel<<<dim3(1, Mrow / 128), 256, SMEM_GEMM>>>(fc2_b, out);
}

// round 9
// speedup vs baseline: 4.4875x; 1.0223x over previous
#include <cuda_runtime.h>
#include <cuda_fp16.h>
#include <math.h>
#include <stdint.h>

// ---------------- problem constants ----------------
#define Bz    64
#define Hh    56
#define Ww    56
#define Cc    192
#define NHh   6
#define WS    7
#define SS    3
#define Nn    49
#define HD    32
#define NW    64
#define Ltok  3136
#define Mrow  200704      // B*L == 128*1568
#define MLPH  768
#define QKVN  576

// ---------------- scratch globals ----------------
__device__ __align__(16) __half g_yw[(size_t)Mrow * Cc];
__device__ __align__(16) __half g_q [(size_t)Mrow * Cc];
__device__ __align__(16) __half g_k [(size_t)Mrow * Cc];
__device__ __align__(16) __half g_v [(size_t)Mrow * Cc];
__device__ __align__(16) __half g_o [(size_t)Mrow * Cc];
__device__ __align__(16) __half g_po[(size_t)Mrow * Cc];   // proj_out+bias, SPATIAL, fp16
__device__ __align__(16) __half g_z [(size_t)Mrow * Cc];   // LN2 out, SPATIAL, fp16

// fp16 weights
__device__ __align__(16) __half g_qkvw[QKVN * Cc];
__device__ __align__(16) __half g_projw[Cc * Cc];
__device__ __align__(16) __half g_fc1w[MLPH * Cc];
__device__ __align__(16) __half g_fc2w[Cc * MLPH];

// ---------------- PTX helpers ----------------
__device__ __forceinline__ uint32_t smem_u32(const void* p) {
    uint32_t a;
    asm("{ .reg .u64 t; cvta.to.shared.u64 t, %1; cvt.u32.u64 %0, t; }"
        : "=r"(a) : "l"(p));
    return a;
}
__device__ __forceinline__ void cp16(uint32_t dst, const void* src) {
    asm volatile("cp.async.cg.shared.global [%0], [%1], 16;"
                 :: "r"(dst), "l"(src));
}
#define CP_COMMIT() asm volatile("cp.async.commit_group;" ::: "memory")
#define CP_WAIT1()  asm volatile("cp.async.wait_group 1;" ::: "memory")
#define CP_WAIT0()  asm volatile("cp.async.wait_group 0;" ::: "memory")

__device__ __forceinline__ void ldm_x4(uint32_t* r, uint32_t a) {
    asm volatile("ldmatrix.sync.aligned.m8n8.x4.shared.b16 {%0,%1,%2,%3}, [%4];"
        : "=r"(r[0]), "=r"(r[1]), "=r"(r[2]), "=r"(r[3]) : "r"(a));
}
__device__ __forceinline__ void ldm_x4t(uint32_t* r, uint32_t a) {
    asm volatile("ldmatrix.sync.aligned.m8n8.x4.trans.shared.b16 {%0,%1,%2,%3}, [%4];"
        : "=r"(r[0]), "=r"(r[1]), "=r"(r[2]), "=r"(r[3]) : "r"(a));
}
__device__ __forceinline__ void mma16816(float* d, const uint32_t* a,
                                         uint32_t b0, uint32_t b1) {
    asm volatile(
        "mma.sync.aligned.m16n8k16.row.col.f32.f16.f16.f32 "
        "{%0,%1,%2,%3}, {%4,%5,%6,%7}, {%8,%9}, {%0,%1,%2,%3};"
        : "+f"(d[0]), "+f"(d[1]), "+f"(d[2]), "+f"(d[3])
        : "r"(a[0]), "r"(a[1]), "r"(a[2]), "r"(a[3]), "r"(b0), "r"(b1));
}
__device__ __forceinline__ uint32_t pack2h(float v0, float v1) {
    __half2 h = __floats2half2_rn(v0, v1);
    return *(uint32_t*)&h;
}

// ---------------- GEMM geometry ----------------
// CTA tile 128(M) x 192(N), warps 2(m) x 4(n), warp tile 64x48.
// K-chunk 64 fp16 = 128B rows, XOR-swizzled (16B-unit: u' = u ^ (row&7)):
// conflict-free cp.async STS + ldmatrix. 3-stage pipeline.
#define GA_BYTES (128 * 128)     // 16384
#define GB_BYTES (192 * 128)     // 24576
#define GSTG     (GA_BYTES + GB_BYTES)
#define SMEM_GEMM (3 * GSTG)     // 122880 (>= 98304 fp32 epi staging)

// attention keeps its own 80B-row layout
#define ASTR   80

__device__ __forceinline__ void gemm_mma(
    const __half* __restrict__ a, const __half* __restrict__ b,
    int K, int n0, float (&acc)[24][4])
{
    extern __shared__ char sm[];
    const uint32_t sb = smem_u32(sm);
    const int tid  = threadIdx.x;
    const int wid  = tid >> 5, lane = tid & 31;
    const int wm   = wid >> 2, wn = wid & 3;
    const int m0   = blockIdx.y * 128;
    const int NCH  = K >> 6;

    #pragma unroll
    for (int i = 0; i < 24; i++)
        #pragma unroll
        for (int j = 0; j < 4; j++) acc[i][j] = 0.f;

    auto load_stage = [&](int stg, int c) {
        const __half* A = a + (size_t)m0 * K + c * 64;
        const __half* B = b + (size_t)n0 * K + c * 64;
        const uint32_t Ab = sb + (uint32_t)stg * GSTG;
        const uint32_t Bb = Ab + GA_BYTES;
        #pragma unroll
        for (int i = 0; i < 4; i++) {              // A: 1024 x 16B
            const int idx = tid + i * 256;
            const int r = idx >> 3, p = idx & 7;
            cp16(Ab + r * 128 + ((p ^ (r & 7)) << 4), A + (size_t)r * K + p * 8);
        }
        #pragma unroll
        for (int i = 0; i < 6; i++) {              // B: 1536 x 16B
            const int idx = tid + i * 256;
            const int r = idx >> 3, p = idx & 7;
            cp16(Bb + r * 128 + ((p ^ (r & 7)) << 4), B + (size_t)r * K + p * 8);
        }
    };

    load_stage(0, 0); CP_COMMIT();
    load_stage(1, 1); CP_COMMIT();

    const int lrow  = lane & 15;
    const int chalf = lane >> 4;

    for (int c = 0; c < NCH; c++) {
        if (c < NCH - 1) { CP_WAIT1(); } else { CP_WAIT0(); }
        __syncthreads();
        const uint32_t Ab = sb + (uint32_t)(c % 3) * GSTG;
        const uint32_t Bb = Ab + GA_BYTES;
        #pragma unroll
        for (int ks = 0; ks < 4; ks++) {
            const int col = ks * 2 + chalf;
            uint32_t rA[4][4], rB[3][4];
            #pragma unroll
            for (int mi = 0; mi < 4; mi++) {
                const int row = wm * 64 + mi * 16 + lrow;
                ldm_x4(rA[mi], Ab + row * 128 + ((col ^ (row & 7)) << 4));
            }
            #pragma unroll
            for (int ni = 0; ni < 3; ni++) {
                const int row = wn * 48 + ni * 16 + lrow;
                ldm_x4(rB[ni], Bb + row * 128 + ((col ^ (row & 7)) << 4));
            }
            #pragma unroll
            for (int mi = 0; mi < 4; mi++)
                #pragma unroll
                for (int nj = 0; nj < 6; nj++)
                    mma16816(acc[mi * 6 + nj], rA[mi],
                             rB[nj >> 1][nj & 1], rB[nj >> 1][(nj & 1) + 2]);
        }
        if (c + 2 < NCH) { load_stage((c + 2) % 3, c + 2); CP_COMMIT(); }
    }
    __syncthreads();   // smem buffers free
}

#define EPI_PROLOGUE()                                          \
    extern __shared__ char sm[];                                \
    const int tid = threadIdx.x;                                \
    const int wid = tid >> 5, lane = tid & 31;                  \
    const int wm = wid >> 2, wn = wid & 3;                      \
    const int g = lane >> 2, tg = lane & 3;                     \
    const int m0 = blockIdx.y * 128;

// ---------------- QKV GEMM + coalesced scatter to fp16 q/k/v -------------
__global__ __launch_bounds__(256) void gemm_qkv_kernel(const float* __restrict__ qkv_b)
{
    float acc[24][4];
    gemm_mma(g_yw, g_qkvw, Cc, blockIdx.x * 192, acc);
    EPI_PROLOGUE();
    const int part = blockIdx.x;  // 0:q 1:k 2:v
    __half* dst = (part == 0) ? g_q : ((part == 1) ? g_k : g_v);
    const float sc = (part == 0) ? 0.17677669529663687f : 1.0f;
    __half* sh = (__half*)sm;   // [128][192]
    #pragma unroll
    for (int t = 0; t < 24; t++) {
        const int mi = t / 6, nj = t % 6;
        const int c = wn * 48 + nj * 8 + tg * 2;
        const float b0 = qkv_b[part * 192 + c];
        const float b1 = qkv_b[part * 192 + c + 1];
        #pragma unroll
        for (int h = 0; h < 2; h++) {
            const int r = wm * 64 + mi * 16 + g + h * 8;
            *(uint32_t*)(sh + r * 192 + c) =
                pack2h((acc[t][h * 2 + 0] + b0) * sc, (acc[t][h * 2 + 1] + b1) * sc);
        }
    }
    __syncthreads();
    #pragma unroll
    for (int i = 0; i < 12; i++) {
        const int idx = tid + i * 256;
        const int r = idx / 24, s = idx - r * 24;
        const int head = s >> 2, d = (s & 3) * 8;
        const int m = m0 + r;
        const int win = m / Nn, n = m - win * Nn;
        const uint4 v = *(const uint4*)(sh + r * 192 + s * 8);
        *(uint4*)(dst + ((size_t)(win * NHh + head) * Nn + n) * HD + d) = v;
    }
}

// ---------------- proj GEMM + FUSED LN2; stores projo(fp16) + z(fp16) -----
__global__ __launch_bounds__(256) void gemm_proj_kernel(
    const float* __restrict__ proj_b, const float* __restrict__ x_shortcut,
    const float* __restrict__ norm2_g, const float* __restrict__ norm2_b)
{
    float acc[24][4];
    gemm_mma(g_o, g_projw, Cc, 0, acc);
    EPI_PROLOGUE();
    float* sh = (float*)sm;    // [128][192] proj_out + bias
    #pragma unroll
    for (int t = 0; t < 24; t++) {
        const int mi = t / 6, nj = t % 6;
        const int cn = wn * 48 + nj * 8 + tg * 2;
        const float b0 = proj_b[cn], b1 = proj_b[cn + 1];
        #pragma unroll
        for (int h = 0; h < 2; h++) {
            const int r = wm * 64 + mi * 16 + g + h * 8;
            *(float2*)(sh + r * 192 + cn) =
                make_float2(acc[t][h * 2 + 0] + b0, acc[t][h * 2 + 1] + b1);
        }
    }
    __syncthreads();
    // warp-per-row: projo(fp16) store; LN over x+projo -> z (spatial order)
    float gg[6], bb[6];
    #pragma unroll
    for (int i = 0; i < 6; i++) {
        gg[i] = norm2_g[lane * 6 + i];
        bb[i] = norm2_b[lane * 6 + i];
    }
    for (int r = wid; r < 128; r += 8) {
        const int m = m0 + r;
        const int win = m / Nn, n = m - win * Nn;
        const int bi = win >> 6, w_ = win & 63;
        const int wr = w_ >> 3, wc = w_ & 7;
        const int pr = n / WS, pc = n - pr * WS;
        int ho = wr * WS + pr + SS; if (ho >= Hh) ho -= Hh;
        int wo = wc * WS + pc + SS; if (wo >= Ww) wo -= Ww;
        const size_t gidx = ((size_t)bi * Ltok + ho * Ww + wo) * Cc;

        float v[6], po[6];
        const float* xr = x_shortcut + gidx + lane * 6;
        const float* sr = sh + r * 192 + lane * 6;
        float2 t0 = *(const float2*)(xr);
        float2 t1 = *(const float2*)(xr + 2);
        float2 t2 = *(const float2*)(xr + 4);
        po[0] = sr[0]; po[1] = sr[1]; po[2] = sr[2];
        po[3] = sr[3]; po[4] = sr[4]; po[5] = sr[5];
        v[0] = t0.x + po[0]; v[1] = t0.y + po[1];
        v[2] = t1.x + po[2]; v[3] = t1.y + po[3];
        v[4] = t2.x + po[4]; v[5] = t2.y + po[5];

        float s = 0.f, ss = 0.f;
        #pragma unroll
        for (int i = 0; i < 6; i++) { s += v[i]; ss += v[i] * v[i]; }
        #pragma unroll
        for (int off = 16; off > 0; off >>= 1) {
            s  += __shfl_xor_sync(0xffffffffu, s,  off);
            ss += __shfl_xor_sync(0xffffffffu, ss, off);
        }
        const float mean = s * (1.f / Cc);
        const float rstd = rsqrtf(ss * (1.f / Cc) - mean * mean + 1e-5f);

        __half* pr_ = g_po + gidx + lane * 6;
        *(uint32_t*)(pr_)     = pack2h(po[0], po[1]);
        *(uint32_t*)(pr_ + 2) = pack2h(po[2], po[3]);
        *(uint32_t*)(pr_ + 4) = pack2h(po[4], po[5]);

        __half* zr = g_z + gidx + lane * 6;
        *(uint32_t*)(zr)     = pack2h((v[0]-mean)*rstd*gg[0]+bb[0], (v[1]-mean)*rstd*gg[1]+bb[1]);
        *(uint32_t*)(zr + 2) = pack2h((v[2]-mean)*rstd*gg[2]+bb[2], (v[3]-mean)*rstd*gg[3]+bb[3]);
        *(uint32_t*)(zr + 4) = pack2h((v[4]-mean)*rstd*gg[4]+bb[4], (v[5]-mean)*rstd*gg[5]+bb[5]);
    }
}

// ---------------- FUSED MLP: fc1 + BN + GELU + fc2 + residual ------------
// hh tile never leaves smem: GELU output written swizzled into the A-buffers
// and consumed as the fc2 A-operand. acc2 persists in registers across the
// 4 hidden sub-tiles.
__global__ __launch_bounds__(256) void gemm_mlp_kernel(
    const float* __restrict__ fc1_b, const float* __restrict__ bn_g,
    const float* __restrict__ bn_b,  const float* __restrict__ fc2_b,
    const float* __restrict__ x_shortcut, float* __restrict__ out)
{
    EPI_PROLOGUE();
    const uint32_t sb = smem_u32(sm);
    const int lrow  = lane & 15;
    const int chalf = lane >> 4;
    const float bnscale = 0.9999950000374997f;  // 1/sqrt(1+1e-5)

    float acc2[24][4];
    #pragma unroll
    for (int i = 0; i < 24; i++)
        #pragma unroll
        for (int j = 0; j < 4; j++) acc2[i][j] = 0.f;

    for (int nt = 0; nt < 4; nt++) {
        // ---- fc1 sub-tile: acc1 = z[m0:,:] @ fc1w[nt*192:,:]^T ----
        float acc1[24][4];
        gemm_mma(g_z, g_fc1w, Cc, nt * 192, acc1);

        // ---- BN + GELU -> fp16 into A-buffers (swizzled, chunked by k) ----
        #pragma unroll
        for (int t = 0; t < 24; t++) {
            const int mi = t / 6, nj = t % 6;
            const int c = wn * 48 + nj * 8 + tg * 2;   // hidden col 0..191
            const int cn = nt * 192 + c;
            const float fb0 = fc1_b[cn],  fb1 = fc1_b[cn + 1];
            const float sg0 = bnscale * bn_g[cn], sg1 = bnscale * bn_g[cn + 1];
            const float bb0 = bn_b[cn], bb1 = bn_b[cn + 1];
            const int j = c >> 6, u = (c & 63) >> 3;
            #pragma unroll
            for (int h = 0; h < 2; h++) {
                const int r = wm * 64 + mi * 16 + g + h * 8;
                float v0 = (acc1[t][h * 2 + 0] + fb0) * sg0 + bb0;
                float v1 = (acc1[t][h * 2 + 1] + fb1) * sg1 + bb1;
                v0 = 0.5f * v0 * (1.f + erff(v0 * 0.70710678118654752f));
                v1 = 0.5f * v1 * (1.f + erff(v1 * 0.70710678118654752f));
                *(uint32_t*)(sm + j * GSTG + r * 128
                             + ((u ^ (r & 7)) << 4) + tg * 4) = pack2h(v0, v1);
            }
        }

        // ---- load fc2w chunks (rows = 192 out channels) into B-buffers ----
        #pragma unroll
        for (int jj = 0; jj < 3; jj++)
            #pragma unroll
            for (int i = 0; i < 6; i++) {
                const int idx = tid + i * 256;
                const int r = idx >> 3, p = idx & 7;
                cp16(sb + jj * GSTG + GA_BYTES + r * 128 + ((p ^ (r & 7)) << 4),
                     g_fc2w + (size_t)r * MLPH + nt * 192 + jj * 64 + p * 8);
            }
        CP_COMMIT(); CP_WAIT0();
        __syncthreads();   // GELU STS + fc2w loads visible

        // ---- fc2 partial: acc2 += hh_tile @ fc2w_tile^T ----
        #pragma unroll
        for (int jj = 0; jj < 3; jj++) {
            const uint32_t Ab = sb + (uint32_t)jj * GSTG;
            const uint32_t Bb = Ab + GA_BYTES;
            #pragma unroll
            for (int ks = 0; ks < 4; ks++) {
                const int col = ks * 2 + chalf;
                uint32_t rA[4][4], rB[3][4];
                #pragma unroll
                for (int mi = 0; mi < 4; mi++) {
                    const int row = wm * 64 + mi * 16 + lrow;
                    ldm_x4(rA[mi], Ab + row * 128 + ((col ^ (row & 7)) << 4));
                }
                #pragma unroll
                for (int ni = 0; ni < 3; ni++) {
                    const int row = wn * 48 + ni * 16 + lrow;
                    ldm_x4(rB[ni], Bb + row * 128 + ((col ^ (row & 7)) << 4));
                }
                #pragma unroll
                for (int mi = 0; mi < 4; mi++)
                    #pragma unroll
                    for (int nj = 0; nj < 6; nj++)
                        mma16816(acc2[mi * 6 + nj], rA[mi],
                                 rB[nj >> 1][nj & 1], rB[nj >> 1][(nj & 1) + 2]);
            }
        }
        __syncthreads();   // buffers free for next nt
    }

    // ---- epilogue: out = x + projo + (acc2 + fc2_b), coalesced ----
    float* shf = (float*)sm;   // [128][192] fp32
    #pragma unroll
    for (int t = 0; t < 24; t++) {
        const int mi = t / 6, nj = t % 6;
        const int cn = wn * 48 + nj * 8 + tg * 2;
        const float b0 = fc2_b[cn], b1 = fc2_b[cn + 1];
        #pragma unroll
        for (int h = 0; h < 2; h++) {
            const int r = wm * 64 + mi * 16 + g + h * 8;
            *(float2*)(shf + r * 192 + cn) =
                make_float2(acc2[t][h * 2 + 0] + b0, acc2[t][h * 2 + 1] + b1);
        }
    }
    __syncthreads();
    #pragma unroll
    for (int i = 0; i < 24; i++) {
        const int idx = tid + i * 256;        // 6144 float4
        const int r = idx / 48, q = idx - r * 48;
        const size_t o = (size_t)(m0 + r) * Cc + q * 4;
        float4 sv = *(const float4*)(shf + r * 192 + q * 4);
        float4 xv = *(const float4*)(x_shortcut + o);
        const uint2 pp = *(const uint2*)(g_po + o);
        const __half2 p0 = *(const __half2*)&pp.x;
        const __half2 p1 = *(const __half2*)&pp.y;
        *(float4*)(out + o) = make_float4(
            xv.x + __low2float(p0)  + sv.x,
            xv.y + __high2float(p0) + sv.y,
            xv.z + __low2float(p1)  + sv.z,
            xv.w + __high2float(p1) + sv.w);
    }
}

// ---------------- HMMA attention: one CTA per (window, head) -------------
#define ATT_SQ 0
#define ATT_SK 5120
#define ATT_SV 10240
#define ATT_SB 15360
#define ATT_BYTES 16064

__global__ __launch_bounds__(128) void attn_kernel(
    const float* __restrict__ rpb, const float* __restrict__ gate)
{
    __shared__ __align__(16) char sm[ATT_BYTES];
    const uint32_t sb0 = smem_u32(sm);
    const int tid = threadIdx.x;
    const int wh = blockIdx.x;
    const int win = wh / NHh, head = wh - win * NHh;
    const size_t base = (size_t)wh * (Nn * HD);

    for (int idx = tid; idx < 392; idx += 128) {
        const int a = idx / 196, e = idx - a * 196;
        const int r = e >> 2, p = e & 3;
        const __half* src = ((a == 0) ? g_q : g_k) + base + r * 32 + p * 8;
        *(uint4*)(sm + a * 5120 + r * ASTR + p * 16) = *(const uint4*)src;
    }
    for (int idx = tid; idx < 196; idx += 128) {
        const int r = idx >> 2, p = idx & 3;
        *(uint4*)(sm + ATT_SV + r * ASTR + p * 16) =
            *(const uint4*)(g_v + base + r * 32 + p * 8);
    }
    if (tid < 60) {
        const int r = 49 + (tid >> 2), p = tid & 3;
        *(uint4*)(sm + ATT_SV + r * ASTR + p * 16) = make_uint4(0, 0, 0, 0);
    }
    float* sbias = (float*)(sm + ATT_SB);
    for (int idx = tid; idx < 169; idx += 128) sbias[idx] = rpb[idx * NHh + head];
    __syncthreads();

    const int wid = tid >> 5, lane = tid & 31;
    const int g = lane >> 2, tg = lane & 3;
    const int lrow = lane & 15;
    const uint32_t koffh = (lane >> 4) << 4;

    float sacc[8][4];
    #pragma unroll
    for (int i = 0; i < 8; i++)
        #pragma unroll
        for (int j = 0; j < 4; j++) sacc[i][j] = 0.f;

    #pragma unroll
    for (int ks = 0; ks < 2; ks++) {
        const uint32_t koff = ks * 32 + koffh;
        uint32_t q[4], k[4][4];
        ldm_x4(q, sb0 + ATT_SQ + (wid * 16 + lrow) * ASTR + koff);
        #pragma unroll
        for (int nt = 0; nt < 4; nt++)
            ldm_x4(k[nt], sb0 + ATT_SK + (nt * 16 + lrow) * ASTR + koff);
        #pragma unroll
        for (int nj = 0; nj < 8; nj++)
            mma16816(sacc[nj], q, k[nj >> 1][nj & 1], k[nj >> 1][(nj & 1) + 2]);
    }

    const int w_ = win & 63;
    const bool er = ((w_ >> 3) == 7), ec = ((w_ & 7) == 7);
    int prr[2], pcc[2], gii[2];
    #pragma unroll
    for (int r = 0; r < 2; r++) {
        const int ii = min(wid * 16 + g + r * 8, 48);
        prr[r] = ii / 7; pcc[r] = ii - prr[r] * 7;
        gii[r] = (er ? ((prr[r] < 4) ? 1 : 2) : 0) * 3
               + (ec ? ((pcc[r] < 4) ? 1 : 2) : 0);
    }
    float mx[2] = {-1e30f, -1e30f};
    #pragma unroll
    for (int nj = 0; nj < 8; nj++)
        #pragma unroll
        for (int e = 0; e < 4; e++) {
            const int r = e >> 1;
            const int j = nj * 8 + tg * 2 + (e & 1);
            float s;
            if (j < Nn) {
                const int rj = j / 7, cj = j - rj * 7;
                const int gj = (er ? ((rj < 4) ? 1 : 2) : 0) * 3
                             + (ec ? ((cj < 4) ? 1 : 2) : 0);
                s = sacc[nj][e] + sbias[(prr[r] - rj + 6) * 13 + (pcc[r] - cj + 6)]
                    + ((gii[r] != gj) ? -100.f : 0.f);
            } else s = -1e30f;
            sacc[nj][e] = s;
            mx[r] = fmaxf(mx[r], s);
        }
    #pragma unroll
    for (int r = 0; r < 2; r++) {
        mx[r] = fmaxf(mx[r], __shfl_xor_sync(0xffffffffu, mx[r], 1));
        mx[r] = fmaxf(mx[r], __shfl_xor_sync(0xffffffffu, mx[r], 2));
    }
    float sum[2] = {0.f, 0.f};
    #pragma unroll
    for (int nj = 0; nj < 8; nj++)
        #pragma unroll
        for (int e = 0; e < 4; e++) {
            const float p = __expf(sacc[nj][e] - mx[e >> 1]);
            sacc[nj][e] = p;
            sum[e >> 1] += p;
        }
    #pragma unroll
    for (int r = 0; r < 2; r++) {
        sum[r] += __shfl_xor_sync(0xffffffffu, sum[r], 1);
        sum[r] += __shfl_xor_sync(0xffffffffu, sum[r], 2);
    }

    uint32_t Ph[8][2];
    #pragma unroll
    for (int nj = 0; nj < 8; nj++)
        #pragma unroll
        for (int r = 0; r < 2; r++)
            Ph[nj][r] = pack2h(sacc[nj][r * 2], sacc[nj][r * 2 + 1]);

    float oacc[4][4];
    #pragma unroll
    for (int i = 0; i < 4; i++)
        #pragma unroll
        for (int j = 0; j < 4; j++) oacc[i][j] = 0.f;

    #pragma unroll
    for (int s = 0; s < 4; s++) {
        uint32_t v0[4], v1[4];
        const uint32_t va = sb0 + ATT_SV + (s * 16 + (lane & 15)) * ASTR
                            + ((lane >> 4) << 4);
        ldm_x4t(v0, va);
        ldm_x4t(v1, va + 32);
        uint32_t aH[4] = {Ph[2*s][0], Ph[2*s][1], Ph[2*s+1][0], Ph[2*s+1][1]};
        mma16816(oacc[0], aH, v0[0], v0[1]);
        mma16816(oacc[1], aH, v0[2], v0[3]);
        mma16816(oacc[2], aH, v1[0], v1[1]);
        mma16816(oacc[3], aH, v1[2], v1[3]);
    }

    const float gval = 1.f / (1.f + expf(-gate[head]));
    #pragma unroll
    for (int r = 0; r < 2; r++) {
        const int i = wid * 16 + g + r * 8;
        if (i < Nn) {
            const float inv = gval / sum[r];
            const size_t rowb = ((size_t)win * Nn + i) * Cc + head * HD;
            #pragma unroll
            for (int nd = 0; nd < 4; nd++) {
                const size_t o = rowb + nd * 8 + tg * 2;
                *(uint32_t*)(g_o + o) = pack2h(oacc[nd][r * 2] * inv,
                                               oacc[nd][r * 2 + 1] * inv);
            }
        }
    }
}

// ---------------- LN1 + shift + window -> fp16 ----------------
__global__ void ln1_shift_window_kernel(const float* __restrict__ x,
                                        const float* __restrict__ g,
                                        const float* __restrict__ b)
{
    const int warp = threadIdx.x >> 5;
    const int lane = threadIdx.x & 31;
    const int t = blockIdx.x * 8 + warp;
    const int win = t / Nn;
    const int n   = t - win * Nn;
    const int bi  = win >> 6;
    const int w_  = win & 63;
    const int wr  = w_ >> 3, wc = w_ & 7;
    const int pr  = n / WS,  pc = n - (n / WS) * WS;
    int srow = wr * WS + pr + SS; if (srow >= Hh) srow -= Hh;
    int scol = wc * WS + pc + SS; if (scol >= Ww) scol -= Ww;
    const float* xp = x + ((size_t)bi * Ltok + srow * Ww + scol) * Cc;

    float v[6], s = 0.f, ss = 0.f;
    #pragma unroll
    for (int kq = 0; kq < 6; kq++) { v[kq] = xp[lane + 32 * kq]; s += v[kq]; ss += v[kq] * v[kq]; }
    #pragma unroll
    for (int off = 16; off > 0; off >>= 1) {
        s  += __shfl_xor_sync(0xffffffffu, s,  off);
        ss += __shfl_xor_sync(0xffffffffu, ss, off);
    }
    const float mean = s * (1.f / Cc);
    const float rstd = rsqrtf(ss * (1.f / Cc) - mean * mean + 1e-5f);
    #pragma unroll
    for (int kq = 0; kq < 6; kq++) {
        const int c = lane + 32 * kq;
        g_yw[(size_t)t * Cc + c] = __float2half((v[kq] - mean) * rstd * g[c] + b[c]);
    }
}

// ---------------- weight fp32 -> fp16 ----------------
__global__ void cvt_kernel(const float* __restrict__ s,
                           __half* __restrict__ h, int n)
{
    const int i = blockIdx.x * 256 + threadIdx.x;
    if (i < n) h[i] = __float2half(s[i]);
}

// ---------------- launch ----------------
extern "C" void kernel_launch(void* const* d_in, const int* in_sizes, int n_in,
                              void* d_out, int out_size)
{
    const float* x       = (const float*)d_in[0];
    const float* norm1_g = (const float*)d_in[1];
    const float* norm1_b = (const float*)d_in[2];
    const float* qkv_w   = (const float*)d_in[3];
    const float* qkv_b   = (const float*)d_in[4];
    const float* rpb     = (const float*)d_in[5];
    const float* gate    = (const float*)d_in[6];
    const float* proj_w  = (const float*)d_in[7];
    const float* proj_b  = (const float*)d_in[8];
    const float* norm2_g = (const float*)d_in[9];
    const float* norm2_b = (const float*)d_in[10];
    const float* fc1_w   = (const float*)d_in[11];
    const float* fc1_b   = (const float*)d_in[12];
    const float* bn_g    = (const float*)d_in[13];
    const float* bn_b    = (const float*)d_in[14];
    const float* fc2_w   = (const float*)d_in[15];
    const float* fc2_b   = (const float*)d_in[16];
    float* out = (float*)d_out;

    static bool attr_done = false;
    if (!attr_done) {
        cudaFuncSetAttribute(gemm_qkv_kernel,  cudaFuncAttributeMaxDynamicSharedMemorySize, SMEM_GEMM);
        cudaFuncSetAttribute(gemm_proj_kernel, cudaFuncAttributeMaxDynamicSharedMemorySize, SMEM_GEMM);
        cudaFuncSetAttribute(gemm_mlp_kernel,  cudaFuncAttributeMaxDynamicSharedMemorySize, SMEM_GEMM);
        attr_done = true;
    }

    __half *qw, *pw, *f1, *f2;
    cudaGetSymbolAddress((void**)&qw, g_qkvw);
    cudaGetSymbolAddress((void**)&pw, g_projw);
    cudaGetSymbolAddress((void**)&f1, g_fc1w);
    cudaGetSymbolAddress((void**)&f2, g_fc2w);

    cvt_kernel<<<(QKVN * Cc + 255) / 256, 256>>>(qkv_w, qw, QKVN * Cc);
    cvt_kernel<<<(Cc * Cc + 255) / 256, 256>>>(proj_w, pw, Cc * Cc);
    cvt_kernel<<<(MLPH * Cc + 255) / 256, 256>>>(fc1_w, f1, MLPH * Cc);
    cvt_kernel<<<(Cc * MLPH + 255) / 256, 256>>>(fc2_w, f2, Cc * MLPH);

    ln1_shift_window_kernel<<<Mrow / 8, 256>>>(x, norm1_g, norm1_b);
    gemm_qkv_kernel<<<dim3(QKVN / 192, Mrow / 128), 256, SMEM_GEMM>>>(qkv_b);
    attn_kernel<<<Bz * NW * NHh, 128>>>(rpb, gate);
    gemm_proj_kernel<<<dim3(1, Mrow / 128), 256, SMEM_GEMM>>>(proj_b, x, norm2_g, norm2_b);
    gemm_mlp_kernel<<<dim3(1, Mrow / 128), 256, SMEM_GEMM>>>(fc1_b, bn_g, bn_b,
                                                             fc2_b, x, out);
}